// round 14
// baseline (speedup 1.0000x reference)
#include <cuda_runtime.h>
#include <cuda_fp16.h>
#include <math.h>
#include <cstdint>

// Problem dims
#define B_   64
#define N_   256
#define D_   1024
#define E_   8
#define BND  (B_*N_*D_)   // 16777216

// ---------------- weight-transpose offsets (elements) ------------------------
#define OFF_TM1  0u
#define OFF_TM2  1048576u
#define OFF_CM1  2097152u
#define OFF_CM2  18874368u
#define OFF_MLP1 35651584u
#define OFF_MLP2 39845888u
#define OFF_ADA  44040192u
#define WT_TOTAL 50331648u

// ---------------- device scratch (allocation-free: __device__ globals) ------
__device__ float g_o[2*BND];                // per-(sample,slot) expert outputs (weighted)
__device__ __half g_a[BND];                 // h / h2 (fp16)  [b][n][d]
__device__ __half g_t[BND];                 // h^T (fp16)     [b][d][n]
__device__ __half g_e[134217728];           // hidden (expert slots / MLP)
__device__ __half g_w[WT_TOTAL];            // transposed fp16 weights [N][K]
__device__ __half g_c[131072];              // silu(c) fp16, padded 128x1024
__device__ float g_mod[B_*6144];
__device__ float g_rinp[B_*64*1024];        // router-input partials [b][slab*8+warp][d]
__device__ float g_probs[B_*E_];
__device__ float g_combine[B_*E_];
__device__ int   g_top1[B_];
__device__ unsigned char g_slot[B_*E_];

// ---------------- math helpers ----------------------------------------------
__device__ __forceinline__ float gelu_f(float x){
    const float c0 = 0.7978845608028654f;
    float x3 = x*x*x;
    float t = tanhf(c0*(x + 0.044715f*x3));
    return 0.5f*x*(1.0f+t);
}
__device__ __forceinline__ float silu_f(float x){ return x / (1.0f + __expf(-x)); }

// ---------------- PTX helpers ------------------------------------------------
__device__ __forceinline__ uint32_t smem_u32(const void* p){
    uint32_t a;
    asm("{ .reg .u64 t; cvta.to.shared.u64 t, %1; cvt.u32.u64 %0, t; }" : "=r"(a) : "l"(p));
    return a;
}
__device__ __forceinline__ void cpa16(uint32_t dst, const void* src){
    asm volatile("cp.async.cg.shared.global [%0], [%1], 16;" :: "r"(dst), "l"(src));
}
#define CP_COMMIT()  asm volatile("cp.async.commit_group;" ::: "memory")
#define CP_WAIT(n)   asm volatile("cp.async.wait_group %0;" :: "n"(n) : "memory")

// fp16 m16n8k16 tensor-core MMA, fp32 accum (baseline PTX)
#define MMA16816(c, a, b) \
    asm volatile("mma.sync.aligned.m16n8k16.row.col.f32.f16.f16.f32 " \
        "{%0,%1,%2,%3}, {%4,%5,%6,%7}, {%8,%9}, {%0,%1,%2,%3};" \
        : "+f"((c)[0]), "+f"((c)[1]), "+f"((c)[2]), "+f"((c)[3]) \
        : "r"((a)[0]), "r"((a)[1]), "r"((a)[2]), "r"((a)[3]), "r"((b)[0]), "r"((b)[1]))

// ldmatrix x4 (baseline PTX, sm_75+)
#define LDSM4(r0,r1,r2,r3,addr) \
    asm volatile("ldmatrix.sync.aligned.m8n8.x4.shared.b16 {%0,%1,%2,%3}, [%4];" \
        : "=r"(r0), "=r"(r1), "=r"(r2), "=r"(r3) : "r"(addr))

// ---------------- tensor GEMM (fp16 single pass, f32 accum) -------------------
// 128x128 block tile, BK=64, 256 threads (8 warps, each 32m x 64n), 2 CTAs/SM.
// 3-stage cp.async pipeline (prefetch depth 2), ONE barrier per chunk.
enum { T_TOK1=0, T_TOK2=1, T_CH1=2, T_CH2=3, T_MLP1=4, T_MLP2=5, T_MOD=6 };

#define TILE_B    18432           // 128 * 144
#define STAGE_B   36864           // 2 tiles (A, B)
#define NSTAGE    3
#define SMEM_BYTES 110592         // 3 stages

__device__ __forceinline__ void ld_chunk(uint32_t sb, int s,
    const __half* A, const __half* Bv,
    int m0, int n0, int k0, int ldk, int tid)
{
    #pragma unroll
    for (int t=0;t<4;t++){
        int j = tid + t*256;
        int r = j >> 3, c16 = j & 7;
        uint32_t d0 = sb + (uint32_t)s*STAGE_B + r*144 + c16*16;
        cpa16(d0,          A  + (size_t)(m0 + r)*ldk + k0 + c16*8);
        cpa16(d0 + TILE_B, Bv + (size_t)(n0 + r)*ldk + k0 + c16*8);
    }
    CP_COMMIT();
}

template<int MODE>
__global__ __launch_bounds__(256,2) void tgemm(const float* __restrict__ bias,
                                               const float* __restrict__ b_ada,
                                               float* __restrict__ outp)
{
    constexpr int Ktot = (MODE==T_TOK1)?256 : (MODE==T_CH2||MODE==T_MLP2)?4096 : 1024;
    constexpr int NC   = Ktot/64;

    const int tid = threadIdx.x;
    const int wid = tid >> 5, lid = tid & 31;
    const int m0 = blockIdx.y*128, n0 = blockIdx.x*128;
    const int warpM = wid & 3, warpN = wid >> 2;
    const int g = lid >> 2, q = lid & 3;

    const __half *A, *Bv;
    const float* be = bias;
    float wgt = 0.f; float* op = nullptr;
    __half* Cp = nullptr;
    constexpr int ldc = (MODE==T_TOK1)?1024 : (MODE==T_CH1||MODE==T_MLP1)?4096 : 1;

    if constexpr (MODE==T_TOK1||MODE==T_TOK2||MODE==T_CH1||MODE==T_CH2){
        int b = blockIdx.z >> 2, e = blockIdx.z & 3;
        int eg = (MODE==T_CH1||MODE==T_CH2) ? 4+e : e;
        unsigned char sl = g_slot[b*E_ + eg];
        if (sl == 255u) return;
        size_t so = (size_t)(b*2 + sl) * 1048576u;
        size_t oo = (size_t)(b*2 + sl) * 262144u;
        if constexpr (MODE==T_TOK1){
            A  = g_t + (size_t)b*262144;
            Bv = g_w + OFF_TM1 + (size_t)e*262144;
            be = bias + e*1024; Cp = g_e + so;
        } else if constexpr (MODE==T_TOK2){
            A  = g_e + so;
            Bv = g_w + OFF_TM2 + (size_t)e*262144;
            be = bias + e*256; op = g_o + oo; wgt = g_combine[b*E_ + eg];
        } else if constexpr (MODE==T_CH1){
            A  = g_a + (size_t)b*262144;
            Bv = g_w + OFF_CM1 + (size_t)e*4194304;
            be = bias + e*4096; Cp = g_e + so;
        } else {
            A  = g_e + so;
            Bv = g_w + OFF_CM2 + (size_t)e*4194304;
            be = bias + e*1024; op = g_o + oo; wgt = g_combine[b*E_ + eg];
        }
    } else if constexpr (MODE==T_MLP1){
        A = g_a; Bv = g_w + OFF_MLP1; Cp = g_e;
    } else if constexpr (MODE==T_MLP2){
        A = g_e; Bv = g_w + OFF_MLP2;
    } else { // T_MOD: silu(c)[128pad x 1024] @ w_ada^T[6144 x 1024]
        A = g_c; Bv = g_w + OFF_ADA;
    }

    extern __shared__ char smem[];
    const uint32_t sbase = smem_u32(smem);

    // per-thread ldmatrix base addresses (stage 0, kk=0)
    const uint32_t aA = sbase + (uint32_t)(warpM*32 + (lid & 15))*144 + ((lid >> 4)*8)*2;
    const uint32_t aB = sbase + TILE_B
                      + (uint32_t)(warpN*64 + ((lid >> 4)*8) + (lid & 7))*144
                      + (((lid >> 3) & 1)*8)*2;

    float acc[2][8][4];
    #pragma unroll
    for (int i=0;i<2;i++)
        #pragma unroll
        for (int j=0;j<8;j++)
            #pragma unroll
            for (int k=0;k<4;k++) acc[i][j][k] = 0.f;

    // prologue: prefetch chunks 0 and 1
    ld_chunk(sbase, 0, A, Bv, m0, n0, 0, Ktot, tid);
    if (NC > 1) ld_chunk(sbase, 1, A, Bv, m0, n0, 64, Ktot, tid);

    int stage = 0;
    for (int c = 0; c < NC; c++){
        if (c + 1 < NC) { CP_WAIT(1); } else { CP_WAIT(0); }
        __syncthreads();   // single barrier per chunk (round-8 scheme)
        if (c + 2 < NC){
            int ws = stage + 2; if (ws >= NSTAGE) ws -= NSTAGE;
            ld_chunk(sbase, ws, A, Bv, m0, n0, (c+2)*64, Ktot, tid);
        }

        const uint32_t sOff = (uint32_t)stage*STAGE_B;

        #pragma unroll
        for (int kk = 0; kk < 64; kk += 16){
            uint32_t af[2][4];
            #pragma unroll
            for (int ma=0;ma<2;ma++){
                uint32_t base = aA + sOff + ma*2304 + kk*2;
                LDSM4(af[ma][0], af[ma][1], af[ma][2], af[ma][3], base);
            }
            uint32_t bf[8][2];
            #pragma unroll
            for (int p=0;p<4;p++){
                uint32_t base = aB + sOff + p*2304 + kk*2;
                LDSM4(bf[2*p][0], bf[2*p][1], bf[2*p+1][0], bf[2*p+1][1], base);
            }
            #pragma unroll
            for (int ma=0;ma<2;ma++)
                #pragma unroll
                for (int nb=0;nb<8;nb++)
                    MMA16816(acc[ma][nb], af[ma], bf[nb]);
        }
        if (++stage == NSTAGE) stage = 0;
    }

    // ---- epilogue ----
    #pragma unroll
    for (int ma=0;ma<2;ma++){
        #pragma unroll
        for (int nb=0;nb<8;nb++){
            int r0 = m0 + warpM*32 + ma*16 + g;
            int nc = n0 + warpN*64 + nb*8 + q*2;
            #pragma unroll
            for (int hv=0;hv<2;hv++){
                int m = r0 + hv*8;
                #pragma unroll
                for (int jj=0;jj<2;jj++){
                    int n = nc + jj;
                    if constexpr (MODE==T_MOD){
                        if (m < B_) g_mod[m*6144 + n] = acc[ma][nb][hv*2+jj];
                        continue;
                    }
                    float v = acc[ma][nb][hv*2+jj] + be[n];
                    if constexpr (MODE==T_TOK1 || MODE==T_CH1 || MODE==T_MLP1){
                        Cp[(size_t)m*ldc + n] = __float2half(gelu_f(v));
                    } else if constexpr (MODE==T_TOK2){
                        op[(size_t)n*D_ + m] = wgt * v;   // m=d, n=token (plain store)
                    } else if constexpr (MODE==T_CH2){
                        op[(size_t)m*D_ + n] = wgt * v;
                    } else { // MLP2
                        int bb = m >> 8;
                        float gml = g_mod[bb*6144 + 5120 + n] + b_ada[5120 + n];
                        size_t o = (size_t)m*D_ + n;
                        outp[o] = outp[o] + gml * v;
                    }
                }
            }
        }
    }
}

// ---------------- merged weight transpose + fp16 convert + csplit -------------
__global__ __launch_bounds__(256) void wconv_all(
    const float* __restrict__ tm_w1, const float* __restrict__ tm_w2,
    const float* __restrict__ cm_w1, const float* __restrict__ cm_w2,
    const float* __restrict__ mlp_w1, const float* __restrict__ mlp_w2,
    const float* __restrict__ w_ada, const float* __restrict__ c,
    __half* __restrict__ wbase)
{
    int t = blockIdx.x;
    if (t >= 49152){                  // csplit range: 128 blocks
        int r = t - 49152;            // 0..127
        int tid = threadIdx.x;
        __half2* dst = reinterpret_cast<__half2*>(&g_c[r*1024 + tid*4]);
        if (r < B_){
            float4 v = *reinterpret_cast<const float4*>(c + (size_t)r*1024 + tid*4);
            dst[0] = __floats2half2_rn(silu_f(v.x), silu_f(v.y));
            dst[1] = __floats2half2_rn(silu_f(v.z), silu_f(v.w));
        } else {
            dst[0] = __floats2half2_rn(0.f, 0.f);
            dst[1] = __floats2half2_rn(0.f, 0.f);
        }
        return;
    }
    const float* src; __half* dst; int R, C, tpz, cpr;
    if (t < 1024)       { src=tm_w1;  dst=wbase+OFF_TM1;  R=256;  C=1024; tpz=256;  cpr=32;  }
    else if (t < 2048)  { t-=1024;  src=tm_w2;  dst=wbase+OFF_TM2;  R=1024; C=256;  tpz=256;  cpr=8;   }
    else if (t < 18432) { t-=2048;  src=cm_w1;  dst=wbase+OFF_CM1;  R=1024; C=4096; tpz=4096; cpr=128; }
    else if (t < 34816) { t-=18432; src=cm_w2;  dst=wbase+OFF_CM2;  R=4096; C=1024; tpz=4096; cpr=32;  }
    else if (t < 38912) { t-=34816; src=mlp_w1; dst=wbase+OFF_MLP1; R=1024; C=4096; tpz=4096; cpr=128; }
    else if (t < 43008) { t-=38912; src=mlp_w2; dst=wbase+OFF_MLP2; R=4096; C=1024; tpz=4096; cpr=32;  }
    else                { t-=43008; src=w_ada;  dst=wbase+OFF_ADA;  R=1024; C=6144; tpz=6144; cpr=192; }
    int z = t / tpz;  t -= z*tpz;
    int rt = t / cpr, ct = t - rt*cpr;
    src += (size_t)z*R*C; dst += (size_t)z*R*C;
    int r0 = rt*32, c0 = ct*32;

    __shared__ float tl[32][33];
    int tx = threadIdx.x & 31, ty = threadIdx.x >> 5;
    #pragma unroll
    for (int i = ty; i < 32; i += 8)
        tl[i][tx] = src[(size_t)(r0+i)*C + c0 + tx];
    __syncthreads();
    #pragma unroll
    for (int i = ty; i < 32; i += 8)
        dst[(size_t)(c0+i)*R + r0 + tx] = __float2half(tl[tx][i]);
}

// ---------------- fused LN+modulate+fp16+transpose+router-partials -----------
// Block = one slab (b, 32 tokens x 1024 d). 256 threads, 8 warps (4 rows each).
#define EW1T_SMEM (32*1026*2)   // fp16 tile [32][1026], 65664 B

__global__ __launch_bounds__(256) void ew1t_kernel(const float* __restrict__ x,
                                                   const float* __restrict__ b_ada){
    int slab = blockIdx.x;            // b*8 + s
    int b = slab >> 3;
    int n0 = (slab & 7) * 32;
    int tid = threadIdx.x, wid = tid >> 5, lane = tid & 31;
    extern __shared__ __half t16[];   // [32][1026]

    float racc[32];
    #pragma unroll
    for (int i=0;i<32;i++) racc[i] = 0.f;

    #pragma unroll
    for (int rr=0; rr<4; rr++){
        int nl = wid*4 + rr;
        int n  = n0 + nl;
        const float4* xr = reinterpret_cast<const float4*>(x + ((size_t)b*256 + n)*1024);
        float4 v[8];
        float s = 0.f, q = 0.f;
        #pragma unroll
        for (int k=0;k<8;k++){
            v[k] = xr[lane + 32*k];
            s += v[k].x+v[k].y+v[k].z+v[k].w;
            q += v[k].x*v[k].x + v[k].y*v[k].y + v[k].z*v[k].z + v[k].w*v[k].w;
        }
        #pragma unroll
        for (int o=16;o;o>>=1){
            s += __shfl_xor_sync(0xffffffffu, s, o);
            q += __shfl_xor_sync(0xffffffffu, q, o);
        }
        float mu  = s*(1.f/1024.f);
        float rstd = rsqrtf(q*(1.f/1024.f) - mu*mu + 1e-6f);
        #pragma unroll
        for (int k=0;k<8;k++){
            int d = (lane + 32*k)*4;
            float4 sm_ = *reinterpret_cast<const float4*>(&g_mod[b*6144 + d]);
            float4 sa  = *reinterpret_cast<const float4*>(&b_ada[d]);
            float4 cm  = *reinterpret_cast<const float4*>(&g_mod[b*6144 + D_ + d]);
            float4 ca  = *reinterpret_cast<const float4*>(&b_ada[D_ + d]);
            float h0 = (v[k].x-mu)*rstd*(1.f+cm.x+ca.x) + sm_.x+sa.x;
            float h1 = (v[k].y-mu)*rstd*(1.f+cm.y+ca.y) + sm_.y+sa.y;
            float h2 = (v[k].z-mu)*rstd*(1.f+cm.z+ca.z) + sm_.z+sa.z;
            float h3 = (v[k].w-mu)*rstd*(1.f+cm.w+ca.w) + sm_.w+sa.w;
            __half2 p0 = __floats2half2_rn(h0,h1);
            __half2 p1 = __floats2half2_rn(h2,h3);
            __half2* ha = reinterpret_cast<__half2*>(&g_a[((size_t)b*256 + n)*1024 + d]);
            ha[0] = p0; ha[1] = p1;
            __half2* ts = reinterpret_cast<__half2*>(&t16[nl*1026 + d]);
            ts[0] = p0; ts[1] = p1;
            racc[k*4+0] += h0; racc[k*4+1] += h1;
            racc[k*4+2] += h2; racc[k*4+3] += h3;
        }
    }
    // router-input partials (exact fp32): one row per (slab, warp)
    {
        float* rp = g_rinp + (size_t)(slab*8 + wid)*1024;
        #pragma unroll
        for (int k=0;k<8;k++){
            int d = (lane + 32*k)*4;
            *reinterpret_cast<float4*>(&rp[d]) =
                make_float4(racc[k*4], racc[k*4+1], racc[k*4+2], racc[k*4+3]);
        }
    }
    __syncthreads();
    // transpose: g_t[b][d][n0+lane] from smem tile
    __half* gt = g_t + (size_t)b*262144;
    for (int dp = wid; dp < 512; dp += 8){
        int d = dp*2;
        __half2 hv = *reinterpret_cast<const __half2*>(&t16[lane*1026 + d]);
        gt[(size_t)d*256     + n0 + lane] = __low2half(hv);
        gt[(size_t)(d+1)*256 + n0 + lane] = __high2half(hv);
    }
}

// ---------------- routing -----------------------------------------------------
__global__ void route_kernel(const float* __restrict__ wr){
    int b = blockIdx.x, tid = threadIdx.x;
    float acc[E_] = {0,0,0,0,0,0,0,0};
    for (int d=tid; d<D_; d+=256){
        float v = 0.f;
        const float* rp = g_rinp + (size_t)b*65536 + d;
        #pragma unroll 8
        for (int p=0;p<64;p++) v += rp[p*1024];
        v *= (1.f/256.f);
        #pragma unroll
        for (int e=0;e<E_;e++) acc[e] = fmaf(v, wr[d*E_ + e], acc[e]);
    }
    __shared__ float red[256];
    __shared__ float slog[E_];
    for (int e=0;e<E_;e++){
        red[tid] = acc[e];
        __syncthreads();
        for (int st=128; st>0; st>>=1){
            if (tid<st) red[tid] += red[tid+st];
            __syncthreads();
        }
        if (tid==0) slog[e] = red[0];
        __syncthreads();
    }
    if (tid==0){
        float p[E_];
        float mx = slog[0];
        for (int e=1;e<E_;e++) mx = fmaxf(mx, slog[e]);
        float ssum = 0.f;
        for (int e=0;e<E_;e++){ p[e] = expf(slog[e]-mx); ssum += p[e]; }
        for (int e=0;e<E_;e++){ p[e] /= ssum; g_probs[b*E_+e] = p[e]; }
        int i0 = 0;
        for (int e=1;e<E_;e++) if (p[e] > p[i0]) i0 = e;
        int i1 = (i0==0) ? 1 : 0;
        for (int e=0;e<E_;e++) if (e!=i0 && p[e] > p[i1]) i1 = e;
        float t = p[i0] + p[i1];
        for (int e=0;e<E_;e++){ g_combine[b*E_+e] = 0.f; g_slot[b*E_+e] = 255u; }
        g_combine[b*E_+i0] = p[i0]/t;  g_slot[b*E_+i0] = 0u;
        g_combine[b*E_+i1] = p[i1]/t;  g_slot[b*E_+i1] = 1u;
        g_top1[b] = i0;
    }
}

__global__ void aux_kernel(float* __restrict__ outp, int out_size){
    if (threadIdx.x != 0) return;
    float meanp[E_]; int cnt[E_];
    for (int e=0;e<E_;e++){ meanp[e]=0.f; cnt[e]=0; }
    for (int b=0;b<B_;b++){
        for (int e=0;e<E_;e++) meanp[e] += g_probs[b*E_+e];
        cnt[g_top1[b]]++;
    }
    float aux = 0.f;
    for (int e=0;e<E_;e++) aux += (meanp[e]*(1.f/B_)) * ((float)cnt[e]*(1.f/B_));
    aux *= (float)E_;
    if (out_size > BND) outp[BND] = aux;
}

// x1 = x + g_msa*(o_slot0 + o_slot1); stage x1 to d_out; h2 -> g_a (fp16)
__global__ void ew2_kernel(const float* __restrict__ x, const float* __restrict__ b_ada,
                           float* __restrict__ outp){
    int r = blockIdx.x, b = r >> 8, tid = threadIdx.x;
    size_t rowo = (size_t)(r & 255)*D_ + tid*4;
    float4 o0 = *reinterpret_cast<const float4*>(g_o + (size_t)(b*2  )*262144 + rowo);
    float4 o1 = *reinterpret_cast<const float4*>(g_o + (size_t)(b*2+1)*262144 + rowo);
    float4 xv = *reinterpret_cast<const float4*>(x + (size_t)r*D_ + tid*4);
    float4 gm = *reinterpret_cast<const float4*>(&g_mod[b*6144 + 2*D_ + tid*4]);
    float4 ga = *reinterpret_cast<const float4*>(&b_ada[2*D_ + tid*4]);
    float v0 = xv.x + (gm.x+ga.x)*(o0.x+o1.x);
    float v1 = xv.y + (gm.y+ga.y)*(o0.y+o1.y);
    float v2 = xv.z + (gm.z+ga.z)*(o0.z+o1.z);
    float v3 = xv.w + (gm.w+ga.w)*(o0.w+o1.w);
    *reinterpret_cast<float4*>(outp + (size_t)r*D_ + tid*4) = make_float4(v0,v1,v2,v3);

    float s = v0+v1+v2+v3;
    float q = v0*v0+v1*v1+v2*v2+v3*v3;
    #pragma unroll
    for (int o=16;o;o>>=1){
        s += __shfl_xor_sync(0xffffffffu, s, o);
        q += __shfl_xor_sync(0xffffffffu, q, o);
    }
    __shared__ float ws[8], wq[8];
    if ((tid & 31) == 0){ ws[tid>>5] = s; wq[tid>>5] = q; }
    __syncthreads();
    s = ws[0]+ws[1]+ws[2]+ws[3]+ws[4]+ws[5]+ws[6]+ws[7];
    q = wq[0]+wq[1]+wq[2]+wq[3]+wq[4]+wq[5]+wq[6]+wq[7];
    float mu  = s*(1.f/1024.f);
    float var = q*(1.f/1024.f) - mu*mu;
    float rstd = rsqrtf(var + 1e-6f);
    float4 sm = *reinterpret_cast<const float4*>(&g_mod[b*6144 + 3*D_ + tid*4]);
    float4 sa = *reinterpret_cast<const float4*>(&b_ada[3*D_ + tid*4]);
    float4 cm = *reinterpret_cast<const float4*>(&g_mod[b*6144 + 4*D_ + tid*4]);
    float4 ca = *reinterpret_cast<const float4*>(&b_ada[4*D_ + tid*4]);
    float h0 = (v0-mu)*rstd*(1.f+cm.x+ca.x) + sm.x+sa.x;
    float h1 = (v1-mu)*rstd*(1.f+cm.y+ca.y) + sm.y+sa.y;
    float h2 = (v2-mu)*rstd*(1.f+cm.z+ca.z) + sm.z+sa.z;
    float h3 = (v3-mu)*rstd*(1.f+cm.w+ca.w) + sm.w+sa.w;
    __half2* ha = reinterpret_cast<__half2*>(&g_a[(size_t)r*D_ + tid*4]);
    ha[0] = __floats2half2_rn(h0,h1);
    ha[1] = __floats2half2_rn(h2,h3);
}

// ---------------- launch ------------------------------------------------------
extern "C" void kernel_launch(void* const* d_in, const int* in_sizes, int n_in,
                              void* d_out, int out_size) {
    const float* x        = (const float*)d_in[0];
    const float* c        = (const float*)d_in[1];
    const float* w_ada    = (const float*)d_in[2];
    const float* b_ada    = (const float*)d_in[3];
    const float* w_router = (const float*)d_in[4];
    const float* tm_w1    = (const float*)d_in[5];
    const float* tm_b1    = (const float*)d_in[6];
    const float* tm_w2    = (const float*)d_in[7];
    const float* tm_b2    = (const float*)d_in[8];
    const float* cm_w1    = (const float*)d_in[9];
    const float* cm_b1    = (const float*)d_in[10];
    const float* cm_w2    = (const float*)d_in[11];
    const float* cm_b2    = (const float*)d_in[12];
    const float* mlp_w1   = (const float*)d_in[13];
    const float* mlp_b1   = (const float*)d_in[14];
    const float* mlp_w2   = (const float*)d_in[15];
    const float* mlp_b2   = (const float*)d_in[16];
    float* outp = (float*)d_out;

    static int attr_done = 0;
    if (!attr_done){
        cudaFuncSetAttribute(tgemm<T_TOK1>, cudaFuncAttributeMaxDynamicSharedMemorySize, SMEM_BYTES);
        cudaFuncSetAttribute(tgemm<T_TOK2>, cudaFuncAttributeMaxDynamicSharedMemorySize, SMEM_BYTES);
        cudaFuncSetAttribute(tgemm<T_CH1>,  cudaFuncAttributeMaxDynamicSharedMemorySize, SMEM_BYTES);
        cudaFuncSetAttribute(tgemm<T_CH2>,  cudaFuncAttributeMaxDynamicSharedMemorySize, SMEM_BYTES);
        cudaFuncSetAttribute(tgemm<T_MLP1>, cudaFuncAttributeMaxDynamicSharedMemorySize, SMEM_BYTES);
        cudaFuncSetAttribute(tgemm<T_MLP2>, cudaFuncAttributeMaxDynamicSharedMemorySize, SMEM_BYTES);
        cudaFuncSetAttribute(tgemm<T_MOD>,  cudaFuncAttributeMaxDynamicSharedMemorySize, SMEM_BYTES);
        cudaFuncSetAttribute(ew1t_kernel,   cudaFuncAttributeMaxDynamicSharedMemorySize, EW1T_SMEM);
        attr_done = 1;
    }

    // weight transpose + fp16 convert + silu(c) (single merged launch)
    __half* wp;
    cudaGetSymbolAddress((void**)&wp, g_w);
    wconv_all<<<49280, 256>>>(tm_w1, tm_w2, cm_w1, cm_w2, mlp_w1, mlp_w2, w_ada, c, wp);

    // adaLN modulation GEMM on tensor cores (writes g_mod directly)
    tgemm<T_MOD><<<dim3(48, 1, 1), 256, SMEM_BYTES>>>(nullptr, nullptr, nullptr);

    // fused LN+modulate+fp16+transpose+router partials
    ew1t_kernel<<<B_*8, 256, EW1T_SMEM>>>(x, b_ada);

    // routing (fp32 — selection identical to reference)
    route_kernel<<<B_, 256>>>(w_router);
    aux_kernel<<<1, 32>>>(outp, out_size);

    // routed experts (fp16 tensor cores, gated per (sample, expert))
    tgemm<T_TOK1><<<dim3( 8, 8, B_*4), 256, SMEM_BYTES>>>(tm_b1, nullptr, nullptr);
    tgemm<T_CH1> <<<dim3(32, 2, B_*4), 256, SMEM_BYTES>>>(cm_b1, nullptr, nullptr);
    tgemm<T_TOK2><<<dim3( 2, 8, B_*4), 256, SMEM_BYTES>>>(tm_b2, nullptr, nullptr);
    tgemm<T_CH2> <<<dim3( 8, 2, B_*4), 256, SMEM_BYTES>>>(cm_b2, nullptr, nullptr);

    // residual + second LN/modulate (x1 staged in d_out)
    ew2_kernel<<<B_*N_, 256>>>(x, b_ada, outp);

    // dense MLP (fp16 tensor cores), second residual fused into MLP2 epilogue
    tgemm<T_MLP1><<<dim3(32, 128, 1), 256, SMEM_BYTES>>>(mlp_b1, nullptr, nullptr);
    tgemm<T_MLP2><<<dim3( 8, 128, 1), 256, SMEM_BYTES>>>(mlp_b2, b_ada, outp);
}

// round 15
// speedup vs baseline: 1.5302x; 1.5302x over previous
#include <cuda_runtime.h>
#include <cuda_fp16.h>
#include <math.h>
#include <cstdint>

// Problem dims
#define B_   64
#define N_   256
#define D_   1024
#define E_   8
#define BND  (B_*N_*D_)   // 16777216

// ---------------- weight-transpose offsets (elements) ------------------------
#define OFF_TM1  0u
#define OFF_TM2  1048576u
#define OFF_CM1  2097152u
#define OFF_CM2  18874368u
#define OFF_MLP1 35651584u
#define OFF_MLP2 39845888u
#define OFF_ADA  44040192u
#define WT_TOTAL 50331648u

// ---------------- device scratch (allocation-free: __device__ globals) ------
__device__ float g_hf[BND];                 // fp32 h (transpose + router source)
__device__ float g_o[2*BND];                // per-(sample,slot) expert outputs (weighted)
__device__ __half g_a[BND];                 // h / h2 (fp16)  [b][n][d]
__device__ __half g_t[BND];                 // h^T (fp16)     [b][d][n]
__device__ __half g_e[134217728];           // hidden (expert slots / MLP)
__device__ __half g_w[WT_TOTAL];            // transposed fp16 weights [N][K]
__device__ __half g_c[131072];              // silu(c) fp16, padded 128x1024
__device__ float g_mod[B_*6144];
__device__ float g_rin[B_*D_];
__device__ float g_probs[B_*E_];
__device__ float g_combine[B_*E_];
__device__ int   g_top1[B_];
__device__ unsigned char g_slot[B_*E_];

// ---------------- math helpers ----------------------------------------------
__device__ __forceinline__ float gelu_f(float x){
    const float c0 = 0.7978845608028654f;
    float x3 = x*x*x;
    float t = tanhf(c0*(x + 0.044715f*x3));
    return 0.5f*x*(1.0f+t);
}
__device__ __forceinline__ float silu_f(float x){ return x / (1.0f + __expf(-x)); }

// ---------------- PTX helpers ------------------------------------------------
__device__ __forceinline__ uint32_t smem_u32(const void* p){
    uint32_t a;
    asm("{ .reg .u64 t; cvta.to.shared.u64 t, %1; cvt.u32.u64 %0, t; }" : "=r"(a) : "l"(p));
    return a;
}
__device__ __forceinline__ void cpa16(uint32_t dst, const void* src){
    asm volatile("cp.async.cg.shared.global [%0], [%1], 16;" :: "r"(dst), "l"(src));
}
#define CP_COMMIT()  asm volatile("cp.async.commit_group;" ::: "memory")
#define CP_WAIT(n)   asm volatile("cp.async.wait_group %0;" :: "n"(n) : "memory")

// fp16 m16n8k16 tensor-core MMA, fp32 accum (baseline PTX)
#define MMA16816(c, a, b) \
    asm volatile("mma.sync.aligned.m16n8k16.row.col.f32.f16.f16.f32 " \
        "{%0,%1,%2,%3}, {%4,%5,%6,%7}, {%8,%9}, {%0,%1,%2,%3};" \
        : "+f"((c)[0]), "+f"((c)[1]), "+f"((c)[2]), "+f"((c)[3]) \
        : "r"((a)[0]), "r"((a)[1]), "r"((a)[2]), "r"((a)[3]), "r"((b)[0]), "r"((b)[1]))

// ldmatrix x4 (baseline PTX, sm_75+)
#define LDSM4(r0,r1,r2,r3,addr) \
    asm volatile("ldmatrix.sync.aligned.m8n8.x4.shared.b16 {%0,%1,%2,%3}, [%4];" \
        : "=r"(r0), "=r"(r1), "=r"(r2), "=r"(r3) : "r"(addr))

// ---------------- tensor GEMM (fp16 single pass, f32 accum) -------------------
// 128x128 block tile, BK=64, 256 threads (8 warps, each 32m x 64n), 2 CTAs/SM.
// 3-stage cp.async pipeline (prefetch depth 2), ONE barrier per chunk.
enum { T_TOK1=0, T_TOK2=1, T_CH1=2, T_CH2=3, T_MLP1=4, T_MLP2=5, T_MOD=6 };

#define TILE_B    18432           // 128 * 144
#define STAGE_B   36864           // 2 tiles (A, B)
#define NSTAGE    3
#define SMEM_BYTES 110592         // 3 stages

__device__ __forceinline__ void ld_chunk(uint32_t sb, int s,
    const __half* A, const __half* Bv,
    int m0, int n0, int k0, int ldk, int tid)
{
    #pragma unroll
    for (int t=0;t<4;t++){
        int j = tid + t*256;
        int r = j >> 3, c16 = j & 7;
        uint32_t d0 = sb + (uint32_t)s*STAGE_B + r*144 + c16*16;
        cpa16(d0,          A  + (size_t)(m0 + r)*ldk + k0 + c16*8);
        cpa16(d0 + TILE_B, Bv + (size_t)(n0 + r)*ldk + k0 + c16*8);
    }
    CP_COMMIT();
}

template<int MODE>
__global__ __launch_bounds__(256,2) void tgemm(const float* __restrict__ bias,
                                               const float* __restrict__ b_ada,
                                               float* __restrict__ outp)
{
    constexpr int Ktot = (MODE==T_TOK1)?256 : (MODE==T_CH2||MODE==T_MLP2)?4096 : 1024;
    constexpr int NC   = Ktot/64;

    const int tid = threadIdx.x;
    const int wid = tid >> 5, lid = tid & 31;
    const int m0 = blockIdx.y*128, n0 = blockIdx.x*128;
    const int warpM = wid & 3, warpN = wid >> 2;
    const int g = lid >> 2, q = lid & 3;

    const __half *A, *Bv;
    const float* be = bias;
    float wgt = 0.f; float* op = nullptr;
    __half* Cp = nullptr;
    constexpr int ldc = (MODE==T_TOK1)?1024 : (MODE==T_CH1||MODE==T_MLP1)?4096 : 1;

    if constexpr (MODE==T_TOK1||MODE==T_TOK2||MODE==T_CH1||MODE==T_CH2){
        int b = blockIdx.z >> 2, e = blockIdx.z & 3;
        int eg = (MODE==T_CH1||MODE==T_CH2) ? 4+e : e;
        unsigned char sl = g_slot[b*E_ + eg];
        if (sl == 255u) return;
        size_t so = (size_t)(b*2 + sl) * 1048576u;
        size_t oo = (size_t)(b*2 + sl) * 262144u;
        if constexpr (MODE==T_TOK1){
            A  = g_t + (size_t)b*262144;
            Bv = g_w + OFF_TM1 + (size_t)e*262144;
            be = bias + e*1024; Cp = g_e + so;
        } else if constexpr (MODE==T_TOK2){
            A  = g_e + so;
            Bv = g_w + OFF_TM2 + (size_t)e*262144;
            be = bias + e*256; op = g_o + oo; wgt = g_combine[b*E_ + eg];
        } else if constexpr (MODE==T_CH1){
            A  = g_a + (size_t)b*262144;
            Bv = g_w + OFF_CM1 + (size_t)e*4194304;
            be = bias + e*4096; Cp = g_e + so;
        } else {
            A  = g_e + so;
            Bv = g_w + OFF_CM2 + (size_t)e*4194304;
            be = bias + e*1024; op = g_o + oo; wgt = g_combine[b*E_ + eg];
        }
    } else if constexpr (MODE==T_MLP1){
        A = g_a; Bv = g_w + OFF_MLP1; Cp = g_e;
    } else if constexpr (MODE==T_MLP2){
        A = g_e; Bv = g_w + OFF_MLP2;
    } else { // T_MOD: silu(c)[128pad x 1024] @ w_ada^T[6144 x 1024]
        A = g_c; Bv = g_w + OFF_ADA;
    }

    extern __shared__ char smem[];
    const uint32_t sbase = smem_u32(smem);

    // per-thread ldmatrix base addresses (stage 0, kk=0)
    const uint32_t aA = sbase + (uint32_t)(warpM*32 + (lid & 15))*144 + ((lid >> 4)*8)*2;
    const uint32_t aB = sbase + TILE_B
                      + (uint32_t)(warpN*64 + ((lid >> 4)*8) + (lid & 7))*144
                      + (((lid >> 3) & 1)*8)*2;

    float acc[2][8][4];
    #pragma unroll
    for (int i=0;i<2;i++)
        #pragma unroll
        for (int j=0;j<8;j++)
            #pragma unroll
            for (int k=0;k<4;k++) acc[i][j][k] = 0.f;

    // prologue: prefetch chunks 0 and 1
    ld_chunk(sbase, 0, A, Bv, m0, n0, 0, Ktot, tid);
    if (NC > 1) ld_chunk(sbase, 1, A, Bv, m0, n0, 64, Ktot, tid);

    int stage = 0;
    for (int c = 0; c < NC; c++){
        if (c + 1 < NC) { CP_WAIT(1); } else { CP_WAIT(0); }
        __syncthreads();   // single barrier per chunk (round-8 scheme)
        if (c + 2 < NC){
            int ws = stage + 2; if (ws >= NSTAGE) ws -= NSTAGE;
            ld_chunk(sbase, ws, A, Bv, m0, n0, (c+2)*64, Ktot, tid);
        }

        const uint32_t sOff = (uint32_t)stage*STAGE_B;

        #pragma unroll
        for (int kk = 0; kk < 64; kk += 16){
            uint32_t af[2][4];
            #pragma unroll
            for (int ma=0;ma<2;ma++){
                uint32_t base = aA + sOff + ma*2304 + kk*2;
                LDSM4(af[ma][0], af[ma][1], af[ma][2], af[ma][3], base);
            }
            uint32_t bf[8][2];
            #pragma unroll
            for (int p=0;p<4;p++){
                uint32_t base = aB + sOff + p*2304 + kk*2;
                LDSM4(bf[2*p][0], bf[2*p][1], bf[2*p+1][0], bf[2*p+1][1], base);
            }
            #pragma unroll
            for (int ma=0;ma<2;ma++)
                #pragma unroll
                for (int nb=0;nb<8;nb++)
                    MMA16816(acc[ma][nb], af[ma], bf[nb]);
        }
        if (++stage == NSTAGE) stage = 0;
    }

    // ---- epilogue ----
    #pragma unroll
    for (int ma=0;ma<2;ma++){
        #pragma unroll
        for (int nb=0;nb<8;nb++){
            int r0 = m0 + warpM*32 + ma*16 + g;
            int nc = n0 + warpN*64 + nb*8 + q*2;
            #pragma unroll
            for (int hv=0;hv<2;hv++){
                int m = r0 + hv*8;
                #pragma unroll
                for (int jj=0;jj<2;jj++){
                    int n = nc + jj;
                    if constexpr (MODE==T_MOD){
                        if (m < B_) g_mod[m*6144 + n] = acc[ma][nb][hv*2+jj];
                        continue;
                    }
                    float v = acc[ma][nb][hv*2+jj] + be[n];
                    if constexpr (MODE==T_TOK1 || MODE==T_CH1 || MODE==T_MLP1){
                        Cp[(size_t)m*ldc + n] = __float2half(gelu_f(v));
                    } else if constexpr (MODE==T_TOK2){
                        op[(size_t)n*D_ + m] = wgt * v;   // m=d, n=token (plain store)
                    } else if constexpr (MODE==T_CH2){
                        op[(size_t)m*D_ + n] = wgt * v;
                    } else { // MLP2
                        int bb = m >> 8;
                        float gml = g_mod[bb*6144 + 5120 + n] + b_ada[5120 + n];
                        size_t o = (size_t)m*D_ + n;
                        outp[o] = outp[o] + gml * v;
                    }
                }
            }
        }
    }
}

// ---------------- merged weight transpose + fp16 convert + csplit -------------
__global__ __launch_bounds__(256) void wconv_all(
    const float* __restrict__ tm_w1, const float* __restrict__ tm_w2,
    const float* __restrict__ cm_w1, const float* __restrict__ cm_w2,
    const float* __restrict__ mlp_w1, const float* __restrict__ mlp_w2,
    const float* __restrict__ w_ada, const float* __restrict__ c,
    __half* __restrict__ wbase)
{
    int t = blockIdx.x;
    if (t >= 49152){                  // csplit range: 128 blocks
        int r = t - 49152;            // 0..127
        int tid = threadIdx.x;
        __half2* dst = reinterpret_cast<__half2*>(&g_c[r*1024 + tid*4]);
        if (r < B_){
            float4 v = *reinterpret_cast<const float4*>(c + (size_t)r*1024 + tid*4);
            dst[0] = __floats2half2_rn(silu_f(v.x), silu_f(v.y));
            dst[1] = __floats2half2_rn(silu_f(v.z), silu_f(v.w));
        } else {
            dst[0] = __floats2half2_rn(0.f, 0.f);
            dst[1] = __floats2half2_rn(0.f, 0.f);
        }
        return;
    }
    const float* src; __half* dst; int R, C, tpz, cpr;
    if (t < 1024)       { src=tm_w1;  dst=wbase+OFF_TM1;  R=256;  C=1024; tpz=256;  cpr=32;  }
    else if (t < 2048)  { t-=1024;  src=tm_w2;  dst=wbase+OFF_TM2;  R=1024; C=256;  tpz=256;  cpr=8;   }
    else if (t < 18432) { t-=2048;  src=cm_w1;  dst=wbase+OFF_CM1;  R=1024; C=4096; tpz=4096; cpr=128; }
    else if (t < 34816) { t-=18432; src=cm_w2;  dst=wbase+OFF_CM2;  R=4096; C=1024; tpz=4096; cpr=32;  }
    else if (t < 38912) { t-=34816; src=mlp_w1; dst=wbase+OFF_MLP1; R=1024; C=4096; tpz=4096; cpr=128; }
    else if (t < 43008) { t-=38912; src=mlp_w2; dst=wbase+OFF_MLP2; R=4096; C=1024; tpz=4096; cpr=32;  }
    else                { t-=43008; src=w_ada;  dst=wbase+OFF_ADA;  R=1024; C=6144; tpz=6144; cpr=192; }
    int z = t / tpz;  t -= z*tpz;
    int rt = t / cpr, ct = t - rt*cpr;
    src += (size_t)z*R*C; dst += (size_t)z*R*C;
    int r0 = rt*32, c0 = ct*32;

    __shared__ float tl[32][33];
    int tx = threadIdx.x & 31, ty = threadIdx.x >> 5;
    #pragma unroll
    for (int i = ty; i < 32; i += 8)
        tl[i][tx] = src[(size_t)(r0+i)*C + c0 + tx];
    __syncthreads();
    #pragma unroll
    for (int i = ty; i < 32; i += 8)
        dst[(size_t)(c0+i)*R + r0 + tx] = __float2half(tl[tx][i]);
}

// ---------------- h^T transpose + fused router-input partial sums -------------
__global__ void tsplit_ht(){   // g_hf [b][n][d] -> g_t [b][d][n]; rin partials
    int z = blockIdx.z;
    const float* src = g_hf + (size_t)z*262144;
    __half* dst = g_t + (size_t)z*262144;
    __shared__ float t[32][33];
    __shared__ float ps[8][32];
    int r0 = blockIdx.y*32, c0 = blockIdx.x*32;   // r=n (256), c=d (1024)
    int tx = threadIdx.x, ty = threadIdx.y;
    float colsum = 0.f;
    #pragma unroll
    for (int i = ty; i < 32; i += 8){
        float v = src[(size_t)(r0+i)*1024 + c0 + tx];
        t[i][tx] = v;
        colsum += v;
    }
    ps[ty][tx] = colsum;
    __syncthreads();
    #pragma unroll
    for (int i = ty; i < 32; i += 8)
        dst[(size_t)(c0+i)*256 + r0 + tx] = __float2half(t[tx][i]);
    if (ty == 0){
        float s = 0.f;
        #pragma unroll
        for (int w=0; w<8; w++) s += ps[w][tx];
        atomicAdd(&g_rin[z*D_ + c0 + tx], s * (1.f/256.f));
    }
}

// ---------------- elementwise / routing kernels ------------------------------
__global__ void ew1_kernel(const float* __restrict__ x, const float* __restrict__ b_ada){
    int r = blockIdx.x, b = r >> 8, tid = threadIdx.x;
    float4 v = *reinterpret_cast<const float4*>(x + (size_t)r*D_ + tid*4);
    float s = v.x+v.y+v.z+v.w;
    float q = v.x*v.x + v.y*v.y + v.z*v.z + v.w*v.w;
    #pragma unroll
    for (int o=16;o;o>>=1){
        s += __shfl_xor_sync(0xffffffffu, s, o);
        q += __shfl_xor_sync(0xffffffffu, q, o);
    }
    __shared__ float ws[8], wq[8];
    if ((tid & 31) == 0){ ws[tid>>5] = s; wq[tid>>5] = q; }
    __syncthreads();
    s = ws[0]+ws[1]+ws[2]+ws[3]+ws[4]+ws[5]+ws[6]+ws[7];
    q = wq[0]+wq[1]+wq[2]+wq[3]+wq[4]+wq[5]+wq[6]+wq[7];
    float mu  = s*(1.f/1024.f);
    float var = q*(1.f/1024.f) - mu*mu;
    float rstd = rsqrtf(var + 1e-6f);
    float4 sm = *reinterpret_cast<const float4*>(&g_mod[b*6144 + tid*4]);
    float4 sa = *reinterpret_cast<const float4*>(&b_ada[tid*4]);
    float4 cm = *reinterpret_cast<const float4*>(&g_mod[b*6144 + D_ + tid*4]);
    float4 ca = *reinterpret_cast<const float4*>(&b_ada[D_ + tid*4]);
    float h0 = (v.x-mu)*rstd*(1.f+cm.x+ca.x) + sm.x+sa.x;
    float h1 = (v.y-mu)*rstd*(1.f+cm.y+ca.y) + sm.y+sa.y;
    float h2 = (v.z-mu)*rstd*(1.f+cm.z+ca.z) + sm.z+sa.z;
    float h3 = (v.w-mu)*rstd*(1.f+cm.w+ca.w) + sm.w+sa.w;
    size_t o = (size_t)r*D_ + tid*4;
    *reinterpret_cast<float4*>(&g_hf[o]) = make_float4(h0,h1,h2,h3);
    __half2* ha = reinterpret_cast<__half2*>(&g_a[o]);
    ha[0] = __floats2half2_rn(h0,h1);
    ha[1] = __floats2half2_rn(h2,h3);
}

__global__ void route_kernel(const float* __restrict__ wr){
    int b = blockIdx.x, tid = threadIdx.x;
    float acc[E_] = {0,0,0,0,0,0,0,0};
    for (int d=tid; d<D_; d+=256){
        float v = g_rin[b*D_ + d];
        #pragma unroll
        for (int e=0;e<E_;e++) acc[e] = fmaf(v, wr[d*E_ + e], acc[e]);
    }
    __shared__ float red[256];
    __shared__ float slog[E_];
    for (int e=0;e<E_;e++){
        red[tid] = acc[e];
        __syncthreads();
        for (int st=128; st>0; st>>=1){
            if (tid<st) red[tid] += red[tid+st];
            __syncthreads();
        }
        if (tid==0) slog[e] = red[0];
        __syncthreads();
    }
    if (tid==0){
        float p[E_];
        float mx = slog[0];
        for (int e=1;e<E_;e++) mx = fmaxf(mx, slog[e]);
        float ssum = 0.f;
        for (int e=0;e<E_;e++){ p[e] = expf(slog[e]-mx); ssum += p[e]; }
        for (int e=0;e<E_;e++){ p[e] /= ssum; g_probs[b*E_+e] = p[e]; }
        int i0 = 0;
        for (int e=1;e<E_;e++) if (p[e] > p[i0]) i0 = e;
        int i1 = (i0==0) ? 1 : 0;
        for (int e=0;e<E_;e++) if (e!=i0 && p[e] > p[i1]) i1 = e;
        float t = p[i0] + p[i1];
        for (int e=0;e<E_;e++){ g_combine[b*E_+e] = 0.f; g_slot[b*E_+e] = 255u; }
        g_combine[b*E_+i0] = p[i0]/t;  g_slot[b*E_+i0] = 0u;
        g_combine[b*E_+i1] = p[i1]/t;  g_slot[b*E_+i1] = 1u;
        g_top1[b] = i0;
    }
}

__global__ void aux_kernel(float* __restrict__ outp, int out_size){
    if (threadIdx.x != 0) return;
    float meanp[E_]; int cnt[E_];
    for (int e=0;e<E_;e++){ meanp[e]=0.f; cnt[e]=0; }
    for (int b=0;b<B_;b++){
        for (int e=0;e<E_;e++) meanp[e] += g_probs[b*E_+e];
        cnt[g_top1[b]]++;
    }
    float aux = 0.f;
    for (int e=0;e<E_;e++) aux += (meanp[e]*(1.f/B_)) * ((float)cnt[e]*(1.f/B_));
    aux *= (float)E_;
    if (out_size > BND) outp[BND] = aux;
}

// x1 = x + g_msa*(o_slot0 + o_slot1); stage x1 to d_out; h2 -> g_a (fp16)
__global__ void ew2_kernel(const float* __restrict__ x, const float* __restrict__ b_ada,
                           float* __restrict__ outp){
    int r = blockIdx.x, b = r >> 8, tid = threadIdx.x;
    size_t rowo = (size_t)(r & 255)*D_ + tid*4;
    float4 o0 = *reinterpret_cast<const float4*>(g_o + (size_t)(b*2  )*262144 + rowo);
    float4 o1 = *reinterpret_cast<const float4*>(g_o + (size_t)(b*2+1)*262144 + rowo);
    float4 xv = *reinterpret_cast<const float4*>(x + (size_t)r*D_ + tid*4);
    float4 gm = *reinterpret_cast<const float4*>(&g_mod[b*6144 + 2*D_ + tid*4]);
    float4 ga = *reinterpret_cast<const float4*>(&b_ada[2*D_ + tid*4]);
    float v0 = xv.x + (gm.x+ga.x)*(o0.x+o1.x);
    float v1 = xv.y + (gm.y+ga.y)*(o0.y+o1.y);
    float v2 = xv.z + (gm.z+ga.z)*(o0.z+o1.z);
    float v3 = xv.w + (gm.w+ga.w)*(o0.w+o1.w);
    *reinterpret_cast<float4*>(outp + (size_t)r*D_ + tid*4) = make_float4(v0,v1,v2,v3);

    float s = v0+v1+v2+v3;
    float q = v0*v0+v1*v1+v2*v2+v3*v3;
    #pragma unroll
    for (int o=16;o;o>>=1){
        s += __shfl_xor_sync(0xffffffffu, s, o);
        q += __shfl_xor_sync(0xffffffffu, q, o);
    }
    __shared__ float ws[8], wq[8];
    if ((tid & 31) == 0){ ws[tid>>5] = s; wq[tid>>5] = q; }
    __syncthreads();
    s = ws[0]+ws[1]+ws[2]+ws[3]+ws[4]+ws[5]+ws[6]+ws[7];
    q = wq[0]+wq[1]+wq[2]+wq[3]+wq[4]+wq[5]+wq[6]+wq[7];
    float mu  = s*(1.f/1024.f);
    float var = q*(1.f/1024.f) - mu*mu;
    float rstd = rsqrtf(var + 1e-6f);
    float4 sm = *reinterpret_cast<const float4*>(&g_mod[b*6144 + 3*D_ + tid*4]);
    float4 sa = *reinterpret_cast<const float4*>(&b_ada[3*D_ + tid*4]);
    float4 cm = *reinterpret_cast<const float4*>(&g_mod[b*6144 + 4*D_ + tid*4]);
    float4 ca = *reinterpret_cast<const float4*>(&b_ada[4*D_ + tid*4]);
    float h0 = (v0-mu)*rstd*(1.f+cm.x+ca.x) + sm.x+sa.x;
    float h1 = (v1-mu)*rstd*(1.f+cm.y+ca.y) + sm.y+sa.y;
    float h2 = (v2-mu)*rstd*(1.f+cm.z+ca.z) + sm.z+sa.z;
    float h3 = (v3-mu)*rstd*(1.f+cm.w+ca.w) + sm.w+sa.w;
    __half2* ha = reinterpret_cast<__half2*>(&g_a[(size_t)r*D_ + tid*4]);
    ha[0] = __floats2half2_rn(h0,h1);
    ha[1] = __floats2half2_rn(h2,h3);
}

// ---------------- launch ------------------------------------------------------
extern "C" void kernel_launch(void* const* d_in, const int* in_sizes, int n_in,
                              void* d_out, int out_size) {
    const float* x        = (const float*)d_in[0];
    const float* c        = (const float*)d_in[1];
    const float* w_ada    = (const float*)d_in[2];
    const float* b_ada    = (const float*)d_in[3];
    const float* w_router = (const float*)d_in[4];
    const float* tm_w1    = (const float*)d_in[5];
    const float* tm_b1    = (const float*)d_in[6];
    const float* tm_w2    = (const float*)d_in[7];
    const float* tm_b2    = (const float*)d_in[8];
    const float* cm_w1    = (const float*)d_in[9];
    const float* cm_b1    = (const float*)d_in[10];
    const float* cm_w2    = (const float*)d_in[11];
    const float* cm_b2    = (const float*)d_in[12];
    const float* mlp_w1   = (const float*)d_in[13];
    const float* mlp_b1   = (const float*)d_in[14];
    const float* mlp_w2   = (const float*)d_in[15];
    const float* mlp_b2   = (const float*)d_in[16];
    float* outp = (float*)d_out;

    static int attr_done = 0;
    if (!attr_done){
        cudaFuncSetAttribute(tgemm<T_TOK1>, cudaFuncAttributeMaxDynamicSharedMemorySize, SMEM_BYTES);
        cudaFuncSetAttribute(tgemm<T_TOK2>, cudaFuncAttributeMaxDynamicSharedMemorySize, SMEM_BYTES);
        cudaFuncSetAttribute(tgemm<T_CH1>,  cudaFuncAttributeMaxDynamicSharedMemorySize, SMEM_BYTES);
        cudaFuncSetAttribute(tgemm<T_CH2>,  cudaFuncAttributeMaxDynamicSharedMemorySize, SMEM_BYTES);
        cudaFuncSetAttribute(tgemm<T_MLP1>, cudaFuncAttributeMaxDynamicSharedMemorySize, SMEM_BYTES);
        cudaFuncSetAttribute(tgemm<T_MLP2>, cudaFuncAttributeMaxDynamicSharedMemorySize, SMEM_BYTES);
        cudaFuncSetAttribute(tgemm<T_MOD>,  cudaFuncAttributeMaxDynamicSharedMemorySize, SMEM_BYTES);
        attr_done = 1;
    }

    // zero g_rin via async memset (graph-capturable)
    void *rinp;
    cudaGetSymbolAddress(&rinp, g_rin);
    cudaMemsetAsync(rinp, 0, B_*D_*sizeof(float));

    // weight transpose + fp16 convert + silu(c) (single merged launch)
    __half* wp;
    cudaGetSymbolAddress((void**)&wp, g_w);
    wconv_all<<<49280, 256>>>(tm_w1, tm_w2, cm_w1, cm_w2, mlp_w1, mlp_w2, w_ada, c, wp);

    // adaLN modulation GEMM on tensor cores (writes g_mod directly)
    tgemm<T_MOD><<<dim3(48, 1, 1), 256, SMEM_BYTES>>>(nullptr, nullptr, nullptr);

    // LN + modulate; fp16 convert
    ew1_kernel<<<B_*N_, 256>>>(x, b_ada);
    // h^T fp16 for token experts + fused router-input partial sums
    tsplit_ht<<<dim3(32, 8, 64), dim3(32,8)>>>();

    // routing (fp32 — selection identical to reference)
    route_kernel<<<B_, 256>>>(w_router);
    aux_kernel<<<1, 32>>>(outp, out_size);

    // routed experts (fp16 tensor cores, gated per (sample, expert))
    tgemm<T_TOK1><<<dim3( 8, 8, B_*4), 256, SMEM_BYTES>>>(tm_b1, nullptr, nullptr);
    tgemm<T_CH1> <<<dim3(32, 2, B_*4), 256, SMEM_BYTES>>>(cm_b1, nullptr, nullptr);
    tgemm<T_TOK2><<<dim3( 2, 8, B_*4), 256, SMEM_BYTES>>>(tm_b2, nullptr, nullptr);
    tgemm<T_CH2> <<<dim3( 8, 2, B_*4), 256, SMEM_BYTES>>>(cm_b2, nullptr, nullptr);

    // residual + second LN/modulate (x1 staged in d_out)
    ew2_kernel<<<B_*N_, 256>>>(x, b_ada, outp);

    // dense MLP (fp16 tensor cores), second residual fused into MLP2 epilogue
    tgemm<T_MLP1><<<dim3(32, 128, 1), 256, SMEM_BYTES>>>(mlp_b1, nullptr, nullptr);
    tgemm<T_MLP2><<<dim3( 8, 128, 1), 256, SMEM_BYTES>>>(mlp_b2, b_ada, outp);
}

// round 16
// speedup vs baseline: 1.5328x; 1.0017x over previous
#include <cuda_runtime.h>
#include <cuda_fp16.h>
#include <math.h>
#include <cstdint>

// Problem dims
#define B_   64
#define N_   256
#define D_   1024
#define E_   8
#define BND  (B_*N_*D_)   // 16777216

// ---------------- weight-transpose offsets (elements) ------------------------
#define OFF_TM1  0u
#define OFF_TM2  1048576u
#define OFF_CM1  2097152u
#define OFF_CM2  18874368u
#define OFF_MLP1 35651584u
#define OFF_MLP2 39845888u
#define OFF_ADA  44040192u
#define WT_TOTAL 50331648u

// ---------------- device scratch (allocation-free: __device__ globals) ------
__device__ float g_hf[BND];                 // fp32 h (transpose + router source)
__device__ __half g_o2[2*BND];              // per-(sample,slot) expert outputs (fp16)
__device__ __half g_a[BND];                 // h / h2 (fp16)  [b][n][d]
__device__ __half g_t[BND];                 // h^T (fp16)     [b][d][n]
__device__ __half g_e[134217728];           // hidden (expert slots / MLP)
__device__ __half g_w[WT_TOTAL];            // transposed fp16 weights [N][K]
__device__ __half g_c[131072];              // silu(c) fp16, padded 128x1024
__device__ float g_mod[B_*6144];
__device__ float g_rin[B_*D_];
__device__ float g_probs[B_*E_];
__device__ float g_combine[B_*E_];
__device__ int   g_top1[B_];
__device__ unsigned char g_slot[B_*E_];

// ---------------- math helpers ----------------------------------------------
__device__ __forceinline__ float gelu_f(float x){
    const float c0 = 0.7978845608028654f;
    float x3 = x*x*x;
    float t = tanhf(c0*(x + 0.044715f*x3));
    return 0.5f*x*(1.0f+t);
}
__device__ __forceinline__ float silu_f(float x){ return x / (1.0f + __expf(-x)); }

// ---------------- PTX helpers ------------------------------------------------
__device__ __forceinline__ uint32_t smem_u32(const void* p){
    uint32_t a;
    asm("{ .reg .u64 t; cvta.to.shared.u64 t, %1; cvt.u32.u64 %0, t; }" : "=r"(a) : "l"(p));
    return a;
}
__device__ __forceinline__ void cpa16(uint32_t dst, const void* src){
    asm volatile("cp.async.cg.shared.global [%0], [%1], 16;" :: "r"(dst), "l"(src));
}
#define CP_COMMIT()  asm volatile("cp.async.commit_group;" ::: "memory")
#define CP_WAIT(n)   asm volatile("cp.async.wait_group %0;" :: "n"(n) : "memory")

// fp16 m16n8k16 tensor-core MMA, fp32 accum (baseline PTX)
#define MMA16816(c, a, b) \
    asm volatile("mma.sync.aligned.m16n8k16.row.col.f32.f16.f16.f32 " \
        "{%0,%1,%2,%3}, {%4,%5,%6,%7}, {%8,%9}, {%0,%1,%2,%3};" \
        : "+f"((c)[0]), "+f"((c)[1]), "+f"((c)[2]), "+f"((c)[3]) \
        : "r"((a)[0]), "r"((a)[1]), "r"((a)[2]), "r"((a)[3]), "r"((b)[0]), "r"((b)[1]))

// ldmatrix x4 (baseline PTX, sm_75+)
#define LDSM4(r0,r1,r2,r3,addr) \
    asm volatile("ldmatrix.sync.aligned.m8n8.x4.shared.b16 {%0,%1,%2,%3}, [%4];" \
        : "=r"(r0), "=r"(r1), "=r"(r2), "=r"(r3) : "r"(addr))

// ---------------- tensor GEMM (fp16 single pass, f32 accum) -------------------
// 128x128 block tile, BK=64, 256 threads (8 warps, each 32m x 64n), 2 CTAs/SM.
// 3-stage cp.async pipeline (prefetch depth 2), ONE barrier per chunk.
enum { T_TOK1=0, T_TOK2=1, T_CH1=2, T_CH2=3, T_MLP1=4, T_MLP2=5, T_MOD=6 };

#define TILE_B    18432           // 128 * 144
#define STAGE_B   36864           // 2 tiles (A, B)
#define NSTAGE    3
#define SMEM_BYTES 110592         // 3 stages

__device__ __forceinline__ void ld_chunk(uint32_t sb, int s,
    const __half* A, const __half* Bv,
    int m0, int n0, int k0, int ldk, int tid)
{
    #pragma unroll
    for (int t=0;t<4;t++){
        int j = tid + t*256;
        int r = j >> 3, c16 = j & 7;
        uint32_t d0 = sb + (uint32_t)s*STAGE_B + r*144 + c16*16;
        cpa16(d0,          A  + (size_t)(m0 + r)*ldk + k0 + c16*8);
        cpa16(d0 + TILE_B, Bv + (size_t)(n0 + r)*ldk + k0 + c16*8);
    }
    CP_COMMIT();
}

template<int MODE>
__global__ __launch_bounds__(256,2) void tgemm(const float* __restrict__ bias,
                                               const float* __restrict__ b_ada,
                                               float* __restrict__ outp)
{
    constexpr int Ktot = (MODE==T_TOK1)?256 : (MODE==T_CH2||MODE==T_MLP2)?4096 : 1024;
    constexpr int NC   = Ktot/64;

    const int tid = threadIdx.x;
    const int wid = tid >> 5, lid = tid & 31;
    const int m0 = blockIdx.y*128, n0 = blockIdx.x*128;
    const int warpM = wid & 3, warpN = wid >> 2;
    const int g = lid >> 2, q = lid & 3;

    const __half *A, *Bv;
    const float* be = bias;
    float wgt = 0.f; __half* op = nullptr;
    __half* Cp = nullptr;
    constexpr int ldc = (MODE==T_TOK1)?1024 : (MODE==T_CH1||MODE==T_MLP1)?4096 : 1;

    if constexpr (MODE==T_TOK1||MODE==T_TOK2||MODE==T_CH1||MODE==T_CH2){
        int b = blockIdx.z >> 2, e = blockIdx.z & 3;
        int eg = (MODE==T_CH1||MODE==T_CH2) ? 4+e : e;
        unsigned char sl = g_slot[b*E_ + eg];
        if (sl == 255u) return;
        size_t so = (size_t)(b*2 + sl) * 1048576u;
        size_t oo = (size_t)(b*2 + sl) * 262144u;
        if constexpr (MODE==T_TOK1){
            A  = g_t + (size_t)b*262144;
            Bv = g_w + OFF_TM1 + (size_t)e*262144;
            be = bias + e*1024; Cp = g_e + so;
        } else if constexpr (MODE==T_TOK2){
            A  = g_e + so;
            Bv = g_w + OFF_TM2 + (size_t)e*262144;
            be = bias + e*256; op = g_o2 + oo; wgt = g_combine[b*E_ + eg];
        } else if constexpr (MODE==T_CH1){
            A  = g_a + (size_t)b*262144;
            Bv = g_w + OFF_CM1 + (size_t)e*4194304;
            be = bias + e*4096; Cp = g_e + so;
        } else {
            A  = g_e + so;
            Bv = g_w + OFF_CM2 + (size_t)e*4194304;
            be = bias + e*1024; op = g_o2 + oo; wgt = g_combine[b*E_ + eg];
        }
    } else if constexpr (MODE==T_MLP1){
        A = g_a; Bv = g_w + OFF_MLP1; Cp = g_e;
    } else if constexpr (MODE==T_MLP2){
        A = g_e; Bv = g_w + OFF_MLP2;
    } else { // T_MOD: silu(c)[128pad x 1024] @ w_ada^T[6144 x 1024]
        A = g_c; Bv = g_w + OFF_ADA;
    }

    extern __shared__ char smem[];
    const uint32_t sbase = smem_u32(smem);

    // per-thread ldmatrix base addresses (stage 0, kk=0)
    const uint32_t aA = sbase + (uint32_t)(warpM*32 + (lid & 15))*144 + ((lid >> 4)*8)*2;
    const uint32_t aB = sbase + TILE_B
                      + (uint32_t)(warpN*64 + ((lid >> 4)*8) + (lid & 7))*144
                      + (((lid >> 3) & 1)*8)*2;

    float acc[2][8][4];
    #pragma unroll
    for (int i=0;i<2;i++)
        #pragma unroll
        for (int j=0;j<8;j++)
            #pragma unroll
            for (int k=0;k<4;k++) acc[i][j][k] = 0.f;

    // prologue: prefetch chunks 0 and 1
    ld_chunk(sbase, 0, A, Bv, m0, n0, 0, Ktot, tid);
    if (NC > 1) ld_chunk(sbase, 1, A, Bv, m0, n0, 64, Ktot, tid);

    int stage = 0;
    for (int c = 0; c < NC; c++){
        if (c + 1 < NC) { CP_WAIT(1); } else { CP_WAIT(0); }
        __syncthreads();   // single barrier per chunk (round-8 scheme)
        if (c + 2 < NC){
            int ws = stage + 2; if (ws >= NSTAGE) ws -= NSTAGE;
            ld_chunk(sbase, ws, A, Bv, m0, n0, (c+2)*64, Ktot, tid);
        }

        const uint32_t sOff = (uint32_t)stage*STAGE_B;

        #pragma unroll
        for (int kk = 0; kk < 64; kk += 16){
            uint32_t af[2][4];
            #pragma unroll
            for (int ma=0;ma<2;ma++){
                uint32_t base = aA + sOff + ma*2304 + kk*2;
                LDSM4(af[ma][0], af[ma][1], af[ma][2], af[ma][3], base);
            }
            uint32_t bf[8][2];
            #pragma unroll
            for (int p=0;p<4;p++){
                uint32_t base = aB + sOff + p*2304 + kk*2;
                LDSM4(bf[2*p][0], bf[2*p][1], bf[2*p+1][0], bf[2*p+1][1], base);
            }
            #pragma unroll
            for (int ma=0;ma<2;ma++)
                #pragma unroll
                for (int nb=0;nb<8;nb++)
                    MMA16816(acc[ma][nb], af[ma], bf[nb]);
        }
        if (++stage == NSTAGE) stage = 0;
    }

    // ---- epilogue ----
    #pragma unroll
    for (int ma=0;ma<2;ma++){
        #pragma unroll
        for (int nb=0;nb<8;nb++){
            int r0 = m0 + warpM*32 + ma*16 + g;
            int nc = n0 + warpN*64 + nb*8 + q*2;
            #pragma unroll
            for (int hv=0;hv<2;hv++){
                int m = r0 + hv*8;
                if constexpr (MODE==T_CH2){
                    // n, n+1 contiguous -> half2 store
                    float v0 = acc[ma][nb][hv*2+0] + be[nc];
                    float v1 = acc[ma][nb][hv*2+1] + be[nc+1];
                    *reinterpret_cast<__half2*>(&op[(size_t)m*D_ + nc]) =
                        __floats2half2_rn(wgt*v0, wgt*v1);
                    continue;
                }
                #pragma unroll
                for (int jj=0;jj<2;jj++){
                    int n = nc + jj;
                    if constexpr (MODE==T_MOD){
                        if (m < B_) g_mod[m*6144 + n] = acc[ma][nb][hv*2+jj];
                        continue;
                    }
                    float v = acc[ma][nb][hv*2+jj] + be[n];
                    if constexpr (MODE==T_TOK1 || MODE==T_CH1 || MODE==T_MLP1){
                        Cp[(size_t)m*ldc + n] = __float2half(gelu_f(v));
                    } else if constexpr (MODE==T_TOK2){
                        op[(size_t)n*D_ + m] = __float2half(wgt * v);  // m=d, n=token
                    } else if constexpr (MODE==T_MLP2){
                        int bb = m >> 8;
                        float gml = g_mod[bb*6144 + 5120 + n] + b_ada[5120 + n];
                        size_t o = (size_t)m*D_ + n;
                        outp[o] = outp[o] + gml * v;
                    }
                }
            }
        }
    }
}

// ---------------- merged weight transpose + fp16 convert + csplit -------------
__global__ __launch_bounds__(256) void wconv_all(
    const float* __restrict__ tm_w1, const float* __restrict__ tm_w2,
    const float* __restrict__ cm_w1, const float* __restrict__ cm_w2,
    const float* __restrict__ mlp_w1, const float* __restrict__ mlp_w2,
    const float* __restrict__ w_ada, const float* __restrict__ c,
    __half* __restrict__ wbase)
{
    int t = blockIdx.x;
    if (t >= 49152){                  // csplit range: 128 blocks
        int r = t - 49152;            // 0..127
        int tid = threadIdx.x;
        __half2* dst = reinterpret_cast<__half2*>(&g_c[r*1024 + tid*4]);
        if (r < B_){
            float4 v = *reinterpret_cast<const float4*>(c + (size_t)r*1024 + tid*4);
            dst[0] = __floats2half2_rn(silu_f(v.x), silu_f(v.y));
            dst[1] = __floats2half2_rn(silu_f(v.z), silu_f(v.w));
        } else {
            dst[0] = __floats2half2_rn(0.f, 0.f);
            dst[1] = __floats2half2_rn(0.f, 0.f);
        }
        return;
    }
    const float* src; __half* dst; int R, C, tpz, cpr;
    if (t < 1024)       { src=tm_w1;  dst=wbase+OFF_TM1;  R=256;  C=1024; tpz=256;  cpr=32;  }
    else if (t < 2048)  { t-=1024;  src=tm_w2;  dst=wbase+OFF_TM2;  R=1024; C=256;  tpz=256;  cpr=8;   }
    else if (t < 18432) { t-=2048;  src=cm_w1;  dst=wbase+OFF_CM1;  R=1024; C=4096; tpz=4096; cpr=128; }
    else if (t < 34816) { t-=18432; src=cm_w2;  dst=wbase+OFF_CM2;  R=4096; C=1024; tpz=4096; cpr=32;  }
    else if (t < 38912) { t-=34816; src=mlp_w1; dst=wbase+OFF_MLP1; R=1024; C=4096; tpz=4096; cpr=128; }
    else if (t < 43008) { t-=38912; src=mlp_w2; dst=wbase+OFF_MLP2; R=4096; C=1024; tpz=4096; cpr=32;  }
    else                { t-=43008; src=w_ada;  dst=wbase+OFF_ADA;  R=1024; C=6144; tpz=6144; cpr=192; }
    int z = t / tpz;  t -= z*tpz;
    int rt = t / cpr, ct = t - rt*cpr;
    src += (size_t)z*R*C; dst += (size_t)z*R*C;
    int r0 = rt*32, c0 = ct*32;

    __shared__ float tl[32][33];
    int tx = threadIdx.x & 31, ty = threadIdx.x >> 5;
    #pragma unroll
    for (int i = ty; i < 32; i += 8)
        tl[i][tx] = src[(size_t)(r0+i)*C + c0 + tx];
    __syncthreads();
    #pragma unroll
    for (int i = ty; i < 32; i += 8)
        dst[(size_t)(c0+i)*R + r0 + tx] = __float2half(tl[tx][i]);
}

// ---------------- h^T transpose + fused router-input partial sums -------------
__global__ void tsplit_ht(){   // g_hf [b][n][d] -> g_t [b][d][n]; rin partials
    int z = blockIdx.z;
    const float* src = g_hf + (size_t)z*262144;
    __half* dst = g_t + (size_t)z*262144;
    __shared__ float t[32][33];
    __shared__ float ps[8][32];
    int r0 = blockIdx.y*32, c0 = blockIdx.x*32;   // r=n (256), c=d (1024)
    int tx = threadIdx.x, ty = threadIdx.y;
    float colsum = 0.f;
    #pragma unroll
    for (int i = ty; i < 32; i += 8){
        float v = src[(size_t)(r0+i)*1024 + c0 + tx];
        t[i][tx] = v;
        colsum += v;
    }
    ps[ty][tx] = colsum;
    __syncthreads();
    #pragma unroll
    for (int i = ty; i < 32; i += 8)
        dst[(size_t)(c0+i)*256 + r0 + tx] = __float2half(t[tx][i]);
    if (ty == 0){
        float s = 0.f;
        #pragma unroll
        for (int w=0; w<8; w++) s += ps[w][tx];
        atomicAdd(&g_rin[z*D_ + c0 + tx], s * (1.f/256.f));
    }
}

// ---------------- elementwise / routing kernels ------------------------------
__global__ void ew1_kernel(const float* __restrict__ x, const float* __restrict__ b_ada){
    int r = blockIdx.x, b = r >> 8, tid = threadIdx.x;
    float4 v = *reinterpret_cast<const float4*>(x + (size_t)r*D_ + tid*4);
    float s = v.x+v.y+v.z+v.w;
    float q = v.x*v.x + v.y*v.y + v.z*v.z + v.w*v.w;
    #pragma unroll
    for (int o=16;o;o>>=1){
        s += __shfl_xor_sync(0xffffffffu, s, o);
        q += __shfl_xor_sync(0xffffffffu, q, o);
    }
    __shared__ float ws[8], wq[8];
    if ((tid & 31) == 0){ ws[tid>>5] = s; wq[tid>>5] = q; }
    __syncthreads();
    s = ws[0]+ws[1]+ws[2]+ws[3]+ws[4]+ws[5]+ws[6]+ws[7];
    q = wq[0]+wq[1]+wq[2]+wq[3]+wq[4]+wq[5]+wq[6]+wq[7];
    float mu  = s*(1.f/1024.f);
    float var = q*(1.f/1024.f) - mu*mu;
    float rstd = rsqrtf(var + 1e-6f);
    float4 sm = *reinterpret_cast<const float4*>(&g_mod[b*6144 + tid*4]);
    float4 sa = *reinterpret_cast<const float4*>(&b_ada[tid*4]);
    float4 cm = *reinterpret_cast<const float4*>(&g_mod[b*6144 + D_ + tid*4]);
    float4 ca = *reinterpret_cast<const float4*>(&b_ada[D_ + tid*4]);
    float h0 = (v.x-mu)*rstd*(1.f+cm.x+ca.x) + sm.x+sa.x;
    float h1 = (v.y-mu)*rstd*(1.f+cm.y+ca.y) + sm.y+sa.y;
    float h2 = (v.z-mu)*rstd*(1.f+cm.z+ca.z) + sm.z+sa.z;
    float h3 = (v.w-mu)*rstd*(1.f+cm.w+ca.w) + sm.w+sa.w;
    size_t o = (size_t)r*D_ + tid*4;
    *reinterpret_cast<float4*>(&g_hf[o]) = make_float4(h0,h1,h2,h3);
    __half2* ha = reinterpret_cast<__half2*>(&g_a[o]);
    ha[0] = __floats2half2_rn(h0,h1);
    ha[1] = __floats2half2_rn(h2,h3);
}

// single-barrier router: per-thread 8 accumulators -> warp shuffle -> smem -> t0
__global__ void route_kernel(const float* __restrict__ wr){
    int b = blockIdx.x, tid = threadIdx.x;
    int wid = tid >> 5, lane = tid & 31;
    float acc[E_] = {0,0,0,0,0,0,0,0};
    for (int d=tid; d<D_; d+=256){
        float v = g_rin[b*D_ + d];
        #pragma unroll
        for (int e=0;e<E_;e++) acc[e] = fmaf(v, wr[d*E_ + e], acc[e]);
    }
    #pragma unroll
    for (int e=0;e<E_;e++)
        #pragma unroll
        for (int o=16;o;o>>=1) acc[e] += __shfl_xor_sync(0xffffffffu, acc[e], o);
    __shared__ float part[8][E_];
    if (lane == 0)
        #pragma unroll
        for (int e=0;e<E_;e++) part[wid][e] = acc[e];
    __syncthreads();
    if (tid == 0){
        float p[E_];
        float slog[E_];
        for (int e=0;e<E_;e++){
            float s = 0.f;
            #pragma unroll
            for (int w=0;w<8;w++) s += part[w][e];
            slog[e] = s;
        }
        float mx = slog[0];
        for (int e=1;e<E_;e++) mx = fmaxf(mx, slog[e]);
        float ssum = 0.f;
        for (int e=0;e<E_;e++){ p[e] = expf(slog[e]-mx); ssum += p[e]; }
        for (int e=0;e<E_;e++){ p[e] /= ssum; g_probs[b*E_+e] = p[e]; }
        int i0 = 0;
        for (int e=1;e<E_;e++) if (p[e] > p[i0]) i0 = e;
        int i1 = (i0==0) ? 1 : 0;
        for (int e=0;e<E_;e++) if (e!=i0 && p[e] > p[i1]) i1 = e;
        float t = p[i0] + p[i1];
        for (int e=0;e<E_;e++){ g_combine[b*E_+e] = 0.f; g_slot[b*E_+e] = 255u; }
        g_combine[b*E_+i0] = p[i0]/t;  g_slot[b*E_+i0] = 0u;
        g_combine[b*E_+i1] = p[i1]/t;  g_slot[b*E_+i1] = 1u;
        g_top1[b] = i0;
    }
}

__global__ void aux_kernel(float* __restrict__ outp, int out_size){
    if (threadIdx.x != 0) return;
    float meanp[E_]; int cnt[E_];
    for (int e=0;e<E_;e++){ meanp[e]=0.f; cnt[e]=0; }
    for (int b=0;b<B_;b++){
        for (int e=0;e<E_;e++) meanp[e] += g_probs[b*E_+e];
        cnt[g_top1[b]]++;
    }
    float aux = 0.f;
    for (int e=0;e<E_;e++) aux += (meanp[e]*(1.f/B_)) * ((float)cnt[e]*(1.f/B_));
    aux *= (float)E_;
    if (out_size > BND) outp[BND] = aux;
}

// x1 = x + g_msa*(o_slot0 + o_slot1); stage x1 to d_out; h2 -> g_a (fp16)
__global__ void ew2_kernel(const float* __restrict__ x, const float* __restrict__ b_ada,
                           float* __restrict__ outp){
    int r = blockIdx.x, b = r >> 8, tid = threadIdx.x;
    size_t rowo = (size_t)(r & 255)*D_ + tid*4;
    const __half2* o0p = reinterpret_cast<const __half2*>(g_o2 + (size_t)(b*2  )*262144 + rowo);
    const __half2* o1p = reinterpret_cast<const __half2*>(g_o2 + (size_t)(b*2+1)*262144 + rowo);
    float2 o0a = __half22float2(o0p[0]), o0b = __half22float2(o0p[1]);
    float2 o1a = __half22float2(o1p[0]), o1b = __half22float2(o1p[1]);
    float4 xv = *reinterpret_cast<const float4*>(x + (size_t)r*D_ + tid*4);
    float4 gm = *reinterpret_cast<const float4*>(&g_mod[b*6144 + 2*D_ + tid*4]);
    float4 ga = *reinterpret_cast<const float4*>(&b_ada[2*D_ + tid*4]);
    float v0 = xv.x + (gm.x+ga.x)*(o0a.x+o1a.x);
    float v1 = xv.y + (gm.y+ga.y)*(o0a.y+o1a.y);
    float v2 = xv.z + (gm.z+ga.z)*(o0b.x+o1b.x);
    float v3 = xv.w + (gm.w+ga.w)*(o0b.y+o1b.y);
    *reinterpret_cast<float4*>(outp + (size_t)r*D_ + tid*4) = make_float4(v0,v1,v2,v3);

    float s = v0+v1+v2+v3;
    float q = v0*v0+v1*v1+v2*v2+v3*v3;
    #pragma unroll
    for (int o=16;o;o>>=1){
        s += __shfl_xor_sync(0xffffffffu, s, o);
        q += __shfl_xor_sync(0xffffffffu, q, o);
    }
    __shared__ float ws[8], wq[8];
    if ((tid & 31) == 0){ ws[tid>>5] = s; wq[tid>>5] = q; }
    __syncthreads();
    s = ws[0]+ws[1]+ws[2]+ws[3]+ws[4]+ws[5]+ws[6]+ws[7];
    q = wq[0]+wq[1]+wq[2]+wq[3]+wq[4]+wq[5]+wq[6]+wq[7];
    float mu  = s*(1.f/1024.f);
    float var = q*(1.f/1024.f) - mu*mu;
    float rstd = rsqrtf(var + 1e-6f);
    float4 sm = *reinterpret_cast<const float4*>(&g_mod[b*6144 + 3*D_ + tid*4]);
    float4 sa = *reinterpret_cast<const float4*>(&b_ada[3*D_ + tid*4]);
    float4 cm = *reinterpret_cast<const float4*>(&g_mod[b*6144 + 4*D_ + tid*4]);
    float4 ca = *reinterpret_cast<const float4*>(&b_ada[4*D_ + tid*4]);
    float h0 = (v0-mu)*rstd*(1.f+cm.x+ca.x) + sm.x+sa.x;
    float h1 = (v1-mu)*rstd*(1.f+cm.y+ca.y) + sm.y+sa.y;
    float h2 = (v2-mu)*rstd*(1.f+cm.z+ca.z) + sm.z+sa.z;
    float h3 = (v3-mu)*rstd*(1.f+cm.w+ca.w) + sm.w+sa.w;
    __half2* ha = reinterpret_cast<__half2*>(&g_a[(size_t)r*D_ + tid*4]);
    ha[0] = __floats2half2_rn(h0,h1);
    ha[1] = __floats2half2_rn(h2,h3);
}

// ---------------- launch ------------------------------------------------------
extern "C" void kernel_launch(void* const* d_in, const int* in_sizes, int n_in,
                              void* d_out, int out_size) {
    const float* x        = (const float*)d_in[0];
    const float* c        = (const float*)d_in[1];
    const float* w_ada    = (const float*)d_in[2];
    const float* b_ada    = (const float*)d_in[3];
    const float* w_router = (const float*)d_in[4];
    const float* tm_w1    = (const float*)d_in[5];
    const float* tm_b1    = (const float*)d_in[6];
    const float* tm_w2    = (const float*)d_in[7];
    const float* tm_b2    = (const float*)d_in[8];
    const float* cm_w1    = (const float*)d_in[9];
    const float* cm_b1    = (const float*)d_in[10];
    const float* cm_w2    = (const float*)d_in[11];
    const float* cm_b2    = (const float*)d_in[12];
    const float* mlp_w1   = (const float*)d_in[13];
    const float* mlp_b1   = (const float*)d_in[14];
    const float* mlp_w2   = (const float*)d_in[15];
    const float* mlp_b2   = (const float*)d_in[16];
    float* outp = (float*)d_out;

    static int attr_done = 0;
    if (!attr_done){
        cudaFuncSetAttribute(tgemm<T_TOK1>, cudaFuncAttributeMaxDynamicSharedMemorySize, SMEM_BYTES);
        cudaFuncSetAttribute(tgemm<T_TOK2>, cudaFuncAttributeMaxDynamicSharedMemorySize, SMEM_BYTES);
        cudaFuncSetAttribute(tgemm<T_CH1>,  cudaFuncAttributeMaxDynamicSharedMemorySize, SMEM_BYTES);
        cudaFuncSetAttribute(tgemm<T_CH2>,  cudaFuncAttributeMaxDynamicSharedMemorySize, SMEM_BYTES);
        cudaFuncSetAttribute(tgemm<T_MLP1>, cudaFuncAttributeMaxDynamicSharedMemorySize, SMEM_BYTES);
        cudaFuncSetAttribute(tgemm<T_MLP2>, cudaFuncAttributeMaxDynamicSharedMemorySize, SMEM_BYTES);
        cudaFuncSetAttribute(tgemm<T_MOD>,  cudaFuncAttributeMaxDynamicSharedMemorySize, SMEM_BYTES);
        attr_done = 1;
    }

    // zero g_rin via async memset (graph-capturable)
    void *rinp;
    cudaGetSymbolAddress(&rinp, g_rin);
    cudaMemsetAsync(rinp, 0, B_*D_*sizeof(float));

    // weight transpose + fp16 convert + silu(c) (single merged launch)
    __half* wp;
    cudaGetSymbolAddress((void**)&wp, g_w);
    wconv_all<<<49280, 256>>>(tm_w1, tm_w2, cm_w1, cm_w2, mlp_w1, mlp_w2, w_ada, c, wp);

    // adaLN modulation GEMM on tensor cores (writes g_mod directly)
    tgemm<T_MOD><<<dim3(48, 1, 1), 256, SMEM_BYTES>>>(nullptr, nullptr, nullptr);

    // LN + modulate; fp16 convert
    ew1_kernel<<<B_*N_, 256>>>(x, b_ada);
    // h^T fp16 for token experts + fused router-input partial sums
    tsplit_ht<<<dim3(32, 8, 64), dim3(32,8)>>>();

    // routing (fp32 — selection identical to reference)
    route_kernel<<<B_, 256>>>(w_router);

    // routed experts (fp16 tensor cores, gated per (sample, expert))
    tgemm<T_TOK1><<<dim3( 8, 8, B_*4), 256, SMEM_BYTES>>>(tm_b1, nullptr, nullptr);
    tgemm<T_CH1> <<<dim3(32, 2, B_*4), 256, SMEM_BYTES>>>(cm_b1, nullptr, nullptr);
    tgemm<T_TOK2><<<dim3( 2, 8, B_*4), 256, SMEM_BYTES>>>(tm_b2, nullptr, nullptr);
    tgemm<T_CH2> <<<dim3( 8, 2, B_*4), 256, SMEM_BYTES>>>(cm_b2, nullptr, nullptr);

    // residual + second LN/modulate (x1 staged in d_out)
    ew2_kernel<<<B_*N_, 256>>>(x, b_ada, outp);

    // dense MLP (fp16 tensor cores), second residual fused into MLP2 epilogue
    tgemm<T_MLP1><<<dim3(32, 128, 1), 256, SMEM_BYTES>>>(mlp_b1, nullptr, nullptr);
    tgemm<T_MLP2><<<dim3( 8, 128, 1), 256, SMEM_BYTES>>>(mlp_b2, b_ada, outp);

    // aux scalar (independent; fills MLP tail)
    aux_kernel<<<1, 32>>>(outp, out_size);
}

// round 17
// speedup vs baseline: 1.5357x; 1.0019x over previous
#include <cuda_runtime.h>
#include <cuda_fp16.h>
#include <math.h>
#include <cstdint>

// Problem dims
#define B_   64
#define N_   256
#define D_   1024
#define E_   8
#define BND  (B_*N_*D_)   // 16777216

// ---------------- weight-transpose offsets (elements) ------------------------
#define OFF_TM1  0u
#define OFF_TM2  1048576u
#define OFF_CM1  2097152u
#define OFF_CM2  18874368u
#define OFF_MLP1 35651584u
#define OFF_MLP2 39845888u
#define OFF_ADA  44040192u
#define WT_TOTAL 50331648u

// ---------------- device scratch (allocation-free: __device__ globals) ------
__device__ float g_hf[BND];                 // fp32 h (transpose + router source)
__device__ __half g_o2[2*BND];              // per-(sample,slot) expert outputs (fp16)
__device__ __half g_a[BND];                 // h / h2 (fp16)  [b][n][d]
__device__ __half g_t[BND];                 // h^T (fp16)     [b][d][n]
__device__ __half g_e[134217728];           // hidden (expert slots / MLP)
__device__ __half g_w[WT_TOTAL];            // transposed fp16 weights [N][K]
__device__ __half g_c[131072];              // silu(c) fp16, padded 128x1024
__device__ float g_mod[B_*6144];
__device__ float g_rin[B_*D_];
__device__ float g_probs[B_*E_];
__device__ float g_combine[B_*E_];
__device__ int   g_top1[B_];
__device__ unsigned char g_slot[B_*E_];

// ---------------- math helpers ----------------------------------------------
__device__ __forceinline__ float gelu_f(float x){
    const float c0 = 0.7978845608028654f;
    float x3 = x*x*x;
    float t = tanhf(c0*(x + 0.044715f*x3));
    return 0.5f*x*(1.0f+t);
}
__device__ __forceinline__ float silu_f(float x){ return x / (1.0f + __expf(-x)); }

// ---------------- PTX helpers ------------------------------------------------
__device__ __forceinline__ uint32_t smem_u32(const void* p){
    uint32_t a;
    asm("{ .reg .u64 t; cvta.to.shared.u64 t, %1; cvt.u32.u64 %0, t; }" : "=r"(a) : "l"(p));
    return a;
}
__device__ __forceinline__ void cpa16(uint32_t dst, const void* src){
    asm volatile("cp.async.cg.shared.global [%0], [%1], 16;" :: "r"(dst), "l"(src));
}
#define CP_COMMIT()  asm volatile("cp.async.commit_group;" ::: "memory")
#define CP_WAIT(n)   asm volatile("cp.async.wait_group %0;" :: "n"(n) : "memory")

// fp16 m16n8k16 tensor-core MMA, fp32 accum (baseline PTX)
#define MMA16816(c, a, b) \
    asm volatile("mma.sync.aligned.m16n8k16.row.col.f32.f16.f16.f32 " \
        "{%0,%1,%2,%3}, {%4,%5,%6,%7}, {%8,%9}, {%0,%1,%2,%3};" \
        : "+f"((c)[0]), "+f"((c)[1]), "+f"((c)[2]), "+f"((c)[3]) \
        : "r"((a)[0]), "r"((a)[1]), "r"((a)[2]), "r"((a)[3]), "r"((b)[0]), "r"((b)[1]))

// ldmatrix x4 (baseline PTX, sm_75+)
#define LDSM4(r0,r1,r2,r3,addr) \
    asm volatile("ldmatrix.sync.aligned.m8n8.x4.shared.b16 {%0,%1,%2,%3}, [%4];" \
        : "=r"(r0), "=r"(r1), "=r"(r2), "=r"(r3) : "r"(addr))

// ---------------- tensor GEMM (fp16 single pass, f32 accum) -------------------
// 128x128 block tile, BK=64, 256 threads (8 warps, each 32m x 64n), 2 CTAs/SM.
// 3-stage cp.async pipeline (prefetch depth 2), ONE barrier per chunk.
enum { T_TOK1=0, T_TOK2=1, T_CH1=2, T_CH2=3, T_MLP1=4, T_MLP2=5, T_MOD=6 };

#define TILE_B    18432           // 128 * 144
#define STAGE_B   36864           // 2 tiles (A, B)
#define NSTAGE    3
#define SMEM_BYTES 110592         // 3 stages

__device__ __forceinline__ void ld_chunk(uint32_t sb, int s,
    const __half* A, const __half* Bv,
    int m0, int n0, int k0, int ldk, int tid)
{
    #pragma unroll
    for (int t=0;t<4;t++){
        int j = tid + t*256;
        int r = j >> 3, c16 = j & 7;
        uint32_t d0 = sb + (uint32_t)s*STAGE_B + r*144 + c16*16;
        cpa16(d0,          A  + (size_t)(m0 + r)*ldk + k0 + c16*8);
        cpa16(d0 + TILE_B, Bv + (size_t)(n0 + r)*ldk + k0 + c16*8);
    }
    CP_COMMIT();
}

template<int MODE>
__global__ __launch_bounds__(256,2) void tgemm(const float* __restrict__ bias,
                                               const float* __restrict__ b_ada,
                                               float* __restrict__ outp)
{
    constexpr int Ktot = (MODE==T_TOK1)?256 : (MODE==T_CH2||MODE==T_MLP2)?4096 : 1024;
    constexpr int NC   = Ktot/64;

    const int tid = threadIdx.x;
    const int wid = tid >> 5, lid = tid & 31;
    const int m0 = blockIdx.y*128, n0 = blockIdx.x*128;
    const int warpM = wid & 3, warpN = wid >> 2;
    const int g = lid >> 2, q = lid & 3;

    const __half *A, *Bv;
    const float* be = bias;
    float wgt = 0.f; __half* op = nullptr;
    __half* Cp = nullptr;
    constexpr int ldc = (MODE==T_TOK1)?1024 : (MODE==T_CH1||MODE==T_MLP1)?4096 : 1;

    if constexpr (MODE==T_TOK1||MODE==T_TOK2||MODE==T_CH1||MODE==T_CH2){
        int b = blockIdx.z >> 2, e = blockIdx.z & 3;
        int eg = (MODE==T_CH1||MODE==T_CH2) ? 4+e : e;
        unsigned char sl = g_slot[b*E_ + eg];
        if (sl == 255u) return;
        size_t so = (size_t)(b*2 + sl) * 1048576u;
        size_t oo = (size_t)(b*2 + sl) * 262144u;
        if constexpr (MODE==T_TOK1){
            A  = g_t + (size_t)b*262144;
            Bv = g_w + OFF_TM1 + (size_t)e*262144;
            be = bias + e*1024; Cp = g_e + so;
        } else if constexpr (MODE==T_TOK2){
            A  = g_e + so;
            Bv = g_w + OFF_TM2 + (size_t)e*262144;
            be = bias + e*256; op = g_o2 + oo; wgt = g_combine[b*E_ + eg];
        } else if constexpr (MODE==T_CH1){
            A  = g_a + (size_t)b*262144;
            Bv = g_w + OFF_CM1 + (size_t)e*4194304;
            be = bias + e*4096; Cp = g_e + so;
        } else {
            A  = g_e + so;
            Bv = g_w + OFF_CM2 + (size_t)e*4194304;
            be = bias + e*1024; op = g_o2 + oo; wgt = g_combine[b*E_ + eg];
        }
    } else if constexpr (MODE==T_MLP1){
        A = g_a; Bv = g_w + OFF_MLP1; Cp = g_e;
    } else if constexpr (MODE==T_MLP2){
        A = g_e; Bv = g_w + OFF_MLP2;
    } else { // T_MOD: silu(c)[128pad x 1024] @ w_ada^T[6144 x 1024]
        A = g_c; Bv = g_w + OFF_ADA;
    }

    extern __shared__ char smem[];
    const uint32_t sbase = smem_u32(smem);

    // per-thread ldmatrix base addresses (stage 0, kk=0)
    const uint32_t aA = sbase + (uint32_t)(warpM*32 + (lid & 15))*144 + ((lid >> 4)*8)*2;
    const uint32_t aB = sbase + TILE_B
                      + (uint32_t)(warpN*64 + ((lid >> 4)*8) + (lid & 7))*144
                      + (((lid >> 3) & 1)*8)*2;

    float acc[2][8][4];
    #pragma unroll
    for (int i=0;i<2;i++)
        #pragma unroll
        for (int j=0;j<8;j++)
            #pragma unroll
            for (int k=0;k<4;k++) acc[i][j][k] = 0.f;

    // prologue: prefetch chunks 0 and 1
    ld_chunk(sbase, 0, A, Bv, m0, n0, 0, Ktot, tid);
    if (NC > 1) ld_chunk(sbase, 1, A, Bv, m0, n0, 64, Ktot, tid);

    int stage = 0;
    for (int c = 0; c < NC; c++){
        if (c + 1 < NC) { CP_WAIT(1); } else { CP_WAIT(0); }
        __syncthreads();   // single barrier per chunk (round-8 scheme)
        if (c + 2 < NC){
            int ws = stage + 2; if (ws >= NSTAGE) ws -= NSTAGE;
            ld_chunk(sbase, ws, A, Bv, m0, n0, (c+2)*64, Ktot, tid);
        }

        const uint32_t sOff = (uint32_t)stage*STAGE_B;

        #pragma unroll
        for (int kk = 0; kk < 64; kk += 16){
            uint32_t af[2][4];
            #pragma unroll
            for (int ma=0;ma<2;ma++){
                uint32_t base = aA + sOff + ma*2304 + kk*2;
                LDSM4(af[ma][0], af[ma][1], af[ma][2], af[ma][3], base);
            }
            uint32_t bf[8][2];
            #pragma unroll
            for (int p=0;p<4;p++){
                uint32_t base = aB + sOff + p*2304 + kk*2;
                LDSM4(bf[2*p][0], bf[2*p][1], bf[2*p+1][0], bf[2*p+1][1], base);
            }
            #pragma unroll
            for (int ma=0;ma<2;ma++)
                #pragma unroll
                for (int nb=0;nb<8;nb++)
                    MMA16816(acc[ma][nb], af[ma], bf[nb]);
        }
        if (++stage == NSTAGE) stage = 0;
    }

    // ---- epilogue ----
    #pragma unroll
    for (int ma=0;ma<2;ma++){
        #pragma unroll
        for (int nb=0;nb<8;nb++){
            int r0 = m0 + warpM*32 + ma*16 + g;
            int nc = n0 + warpN*64 + nb*8 + q*2;
            #pragma unroll
            for (int hv=0;hv<2;hv++){
                int m = r0 + hv*8;
                if constexpr (MODE==T_CH2){
                    float v0 = acc[ma][nb][hv*2+0] + be[nc];
                    float v1 = acc[ma][nb][hv*2+1] + be[nc+1];
                    *reinterpret_cast<__half2*>(&op[(size_t)m*D_ + nc]) =
                        __floats2half2_rn(wgt*v0, wgt*v1);
                    continue;
                }
                #pragma unroll
                for (int jj=0;jj<2;jj++){
                    int n = nc + jj;
                    if constexpr (MODE==T_MOD){
                        if (m < B_) g_mod[m*6144 + n] = acc[ma][nb][hv*2+jj];
                        continue;
                    }
                    float v = acc[ma][nb][hv*2+jj] + be[n];
                    if constexpr (MODE==T_TOK1 || MODE==T_CH1 || MODE==T_MLP1){
                        Cp[(size_t)m*ldc + n] = __float2half(gelu_f(v));
                    } else if constexpr (MODE==T_TOK2){
                        op[(size_t)n*D_ + m] = __float2half(wgt * v);  // m=d, n=token
                    } else if constexpr (MODE==T_MLP2){
                        int bb = m >> 8;
                        float gml = g_mod[bb*6144 + 5120 + n] + b_ada[5120 + n];
                        size_t o = (size_t)m*D_ + n;
                        outp[o] = outp[o] + gml * v;
                    }
                }
            }
        }
    }
}

// ---------------- expert/MLP weight transpose + fp16 convert (big half) ------
__global__ __launch_bounds__(256) void wconv_w(
    const float* __restrict__ tm_w1, const float* __restrict__ tm_w2,
    const float* __restrict__ cm_w1, const float* __restrict__ cm_w2,
    const float* __restrict__ mlp_w1, const float* __restrict__ mlp_w2,
    __half* __restrict__ wbase)
{
    int t = blockIdx.x;
    const float* src; __half* dst; int R, C, tpz, cpr;
    if (t < 1024)       { src=tm_w1;  dst=wbase+OFF_TM1;  R=256;  C=1024; tpz=256;  cpr=32;  }
    else if (t < 2048)  { t-=1024;  src=tm_w2;  dst=wbase+OFF_TM2;  R=1024; C=256;  tpz=256;  cpr=8;   }
    else if (t < 18432) { t-=2048;  src=cm_w1;  dst=wbase+OFF_CM1;  R=1024; C=4096; tpz=4096; cpr=128; }
    else if (t < 34816) { t-=18432; src=cm_w2;  dst=wbase+OFF_CM2;  R=4096; C=1024; tpz=4096; cpr=32;  }
    else if (t < 38912) { t-=34816; src=mlp_w1; dst=wbase+OFF_MLP1; R=1024; C=4096; tpz=4096; cpr=128; }
    else                { t-=38912; src=mlp_w2; dst=wbase+OFF_MLP2; R=4096; C=1024; tpz=4096; cpr=32;  }
    int z = t / tpz;  t -= z*tpz;
    int rt = t / cpr, ct = t - rt*cpr;
    src += (size_t)z*R*C; dst += (size_t)z*R*C;
    int r0 = rt*32, c0 = ct*32;

    __shared__ float tl[32][33];
    int tx = threadIdx.x & 31, ty = threadIdx.x >> 5;
    #pragma unroll
    for (int i = ty; i < 32; i += 8)
        tl[i][tx] = src[(size_t)(r0+i)*C + c0 + tx];
    __syncthreads();
    #pragma unroll
    for (int i = ty; i < 32; i += 8)
        dst[(size_t)(c0+i)*R + r0 + tx] = __float2half(tl[tx][i]);
}

// ---------------- adaLN weight transpose + csplit (small half, critical path) -
__global__ __launch_bounds__(256) void wconv_a(
    const float* __restrict__ w_ada, const float* __restrict__ c,
    __half* __restrict__ wbase)
{
    int t = blockIdx.x;
    if (t >= 6144){                   // csplit range: 128 blocks
        int r = t - 6144;             // 0..127
        int tid = threadIdx.x;
        __half2* dst = reinterpret_cast<__half2*>(&g_c[r*1024 + tid*4]);
        if (r < B_){
            float4 v = *reinterpret_cast<const float4*>(c + (size_t)r*1024 + tid*4);
            dst[0] = __floats2half2_rn(silu_f(v.x), silu_f(v.y));
            dst[1] = __floats2half2_rn(silu_f(v.z), silu_f(v.w));
        } else {
            dst[0] = __floats2half2_rn(0.f, 0.f);
            dst[1] = __floats2half2_rn(0.f, 0.f);
        }
        return;
    }
    // w_ada: 1024x6144 -> [6144][1024], 192 col-tiles per row-tile
    int rt = t / 192, ct = t - rt*192;
    int r0 = rt*32, c0 = ct*32;
    __shared__ float tl[32][33];
    int tx = threadIdx.x & 31, ty = threadIdx.x >> 5;
    #pragma unroll
    for (int i = ty; i < 32; i += 8)
        tl[i][tx] = w_ada[(size_t)(r0+i)*6144 + c0 + tx];
    __syncthreads();
    __half* dst = wbase + OFF_ADA;
    #pragma unroll
    for (int i = ty; i < 32; i += 8)
        dst[(size_t)(c0+i)*1024 + r0 + tx] = __float2half(tl[tx][i]);
}

// ---------------- h^T transpose + fused router-input partial sums -------------
__global__ void tsplit_ht(){   // g_hf [b][n][d] -> g_t [b][d][n]; rin partials
    int z = blockIdx.z;
    const float* src = g_hf + (size_t)z*262144;
    __half* dst = g_t + (size_t)z*262144;
    __shared__ float t[32][33];
    __shared__ float ps[8][32];
    int r0 = blockIdx.y*32, c0 = blockIdx.x*32;   // r=n (256), c=d (1024)
    int tx = threadIdx.x, ty = threadIdx.y;
    float colsum = 0.f;
    #pragma unroll
    for (int i = ty; i < 32; i += 8){
        float v = src[(size_t)(r0+i)*1024 + c0 + tx];
        t[i][tx] = v;
        colsum += v;
    }
    ps[ty][tx] = colsum;
    __syncthreads();
    #pragma unroll
    for (int i = ty; i < 32; i += 8)
        dst[(size_t)(c0+i)*256 + r0 + tx] = __float2half(t[tx][i]);
    if (ty == 0){
        float s = 0.f;
        #pragma unroll
        for (int w=0; w<8; w++) s += ps[w][tx];
        atomicAdd(&g_rin[z*D_ + c0 + tx], s * (1.f/256.f));
    }
}

// ---------------- elementwise / routing kernels ------------------------------
__global__ void ew1_kernel(const float* __restrict__ x, const float* __restrict__ b_ada){
    int r = blockIdx.x, b = r >> 8, tid = threadIdx.x;
    float4 v = *reinterpret_cast<const float4*>(x + (size_t)r*D_ + tid*4);
    float s = v.x+v.y+v.z+v.w;
    float q = v.x*v.x + v.y*v.y + v.z*v.z + v.w*v.w;
    #pragma unroll
    for (int o=16;o;o>>=1){
        s += __shfl_xor_sync(0xffffffffu, s, o);
        q += __shfl_xor_sync(0xffffffffu, q, o);
    }
    __shared__ float ws[8], wq[8];
    if ((tid & 31) == 0){ ws[tid>>5] = s; wq[tid>>5] = q; }
    __syncthreads();
    s = ws[0]+ws[1]+ws[2]+ws[3]+ws[4]+ws[5]+ws[6]+ws[7];
    q = wq[0]+wq[1]+wq[2]+wq[3]+wq[4]+wq[5]+wq[6]+wq[7];
    float mu  = s*(1.f/1024.f);
    float var = q*(1.f/1024.f) - mu*mu;
    float rstd = rsqrtf(var + 1e-6f);
    float4 sm = *reinterpret_cast<const float4*>(&g_mod[b*6144 + tid*4]);
    float4 sa = *reinterpret_cast<const float4*>(&b_ada[tid*4]);
    float4 cm = *reinterpret_cast<const float4*>(&g_mod[b*6144 + D_ + tid*4]);
    float4 ca = *reinterpret_cast<const float4*>(&b_ada[D_ + tid*4]);
    float h0 = (v.x-mu)*rstd*(1.f+cm.x+ca.x) + sm.x+sa.x;
    float h1 = (v.y-mu)*rstd*(1.f+cm.y+ca.y) + sm.y+sa.y;
    float h2 = (v.z-mu)*rstd*(1.f+cm.z+ca.z) + sm.z+sa.z;
    float h3 = (v.w-mu)*rstd*(1.f+cm.w+ca.w) + sm.w+sa.w;
    size_t o = (size_t)r*D_ + tid*4;
    *reinterpret_cast<float4*>(&g_hf[o]) = make_float4(h0,h1,h2,h3);
    __half2* ha = reinterpret_cast<__half2*>(&g_a[o]);
    ha[0] = __floats2half2_rn(h0,h1);
    ha[1] = __floats2half2_rn(h2,h3);
}

// single-barrier router: per-thread 8 accumulators -> warp shuffle -> smem -> t0
__global__ void route_kernel(const float* __restrict__ wr){
    int b = blockIdx.x, tid = threadIdx.x;
    int wid = tid >> 5, lane = tid & 31;
    float acc[E_] = {0,0,0,0,0,0,0,0};
    for (int d=tid; d<D_; d+=256){
        float v = g_rin[b*D_ + d];
        #pragma unroll
        for (int e=0;e<E_;e++) acc[e] = fmaf(v, wr[d*E_ + e], acc[e]);
    }
    #pragma unroll
    for (int e=0;e<E_;e++)
        #pragma unroll
        for (int o=16;o;o>>=1) acc[e] += __shfl_xor_sync(0xffffffffu, acc[e], o);
    __shared__ float part[8][E_];
    if (lane == 0)
        #pragma unroll
        for (int e=0;e<E_;e++) part[wid][e] = acc[e];
    __syncthreads();
    if (tid == 0){
        float p[E_];
        float slog[E_];
        for (int e=0;e<E_;e++){
            float s = 0.f;
            #pragma unroll
            for (int w=0;w<8;w++) s += part[w][e];
            slog[e] = s;
        }
        float mx = slog[0];
        for (int e=1;e<E_;e++) mx = fmaxf(mx, slog[e]);
        float ssum = 0.f;
        for (int e=0;e<E_;e++){ p[e] = expf(slog[e]-mx); ssum += p[e]; }
        for (int e=0;e<E_;e++){ p[e] /= ssum; g_probs[b*E_+e] = p[e]; }
        int i0 = 0;
        for (int e=1;e<E_;e++) if (p[e] > p[i0]) i0 = e;
        int i1 = (i0==0) ? 1 : 0;
        for (int e=0;e<E_;e++) if (e!=i0 && p[e] > p[i1]) i1 = e;
        float t = p[i0] + p[i1];
        for (int e=0;e<E_;e++){ g_combine[b*E_+e] = 0.f; g_slot[b*E_+e] = 255u; }
        g_combine[b*E_+i0] = p[i0]/t;  g_slot[b*E_+i0] = 0u;
        g_combine[b*E_+i1] = p[i1]/t;  g_slot[b*E_+i1] = 1u;
        g_top1[b] = i0;
    }
}

__global__ void aux_kernel(float* __restrict__ outp, int out_size){
    if (threadIdx.x != 0) return;
    float meanp[E_]; int cnt[E_];
    for (int e=0;e<E_;e++){ meanp[e]=0.f; cnt[e]=0; }
    for (int b=0;b<B_;b++){
        for (int e=0;e<E_;e++) meanp[e] += g_probs[b*E_+e];
        cnt[g_top1[b]]++;
    }
    float aux = 0.f;
    for (int e=0;e<E_;e++) aux += (meanp[e]*(1.f/B_)) * ((float)cnt[e]*(1.f/B_));
    aux *= (float)E_;
    if (out_size > BND) outp[BND] = aux;
}

// x1 = x + g_msa*(o_slot0 + o_slot1); stage x1 to d_out; h2 -> g_a (fp16)
__global__ void ew2_kernel(const float* __restrict__ x, const float* __restrict__ b_ada,
                           float* __restrict__ outp){
    int r = blockIdx.x, b = r >> 8, tid = threadIdx.x;
    size_t rowo = (size_t)(r & 255)*D_ + tid*4;
    const __half2* o0p = reinterpret_cast<const __half2*>(g_o2 + (size_t)(b*2  )*262144 + rowo);
    const __half2* o1p = reinterpret_cast<const __half2*>(g_o2 + (size_t)(b*2+1)*262144 + rowo);
    float2 o0a = __half22float2(o0p[0]), o0b = __half22float2(o0p[1]);
    float2 o1a = __half22float2(o1p[0]), o1b = __half22float2(o1p[1]);
    float4 xv = *reinterpret_cast<const float4*>(x + (size_t)r*D_ + tid*4);
    float4 gm = *reinterpret_cast<const float4*>(&g_mod[b*6144 + 2*D_ + tid*4]);
    float4 ga = *reinterpret_cast<const float4*>(&b_ada[2*D_ + tid*4]);
    float v0 = xv.x + (gm.x+ga.x)*(o0a.x+o1a.x);
    float v1 = xv.y + (gm.y+ga.y)*(o0a.y+o1a.y);
    float v2 = xv.z + (gm.z+ga.z)*(o0b.x+o1b.x);
    float v3 = xv.w + (gm.w+ga.w)*(o0b.y+o1b.y);
    *reinterpret_cast<float4*>(outp + (size_t)r*D_ + tid*4) = make_float4(v0,v1,v2,v3);

    float s = v0+v1+v2+v3;
    float q = v0*v0+v1*v1+v2*v2+v3*v3;
    #pragma unroll
    for (int o=16;o;o>>=1){
        s += __shfl_xor_sync(0xffffffffu, s, o);
        q += __shfl_xor_sync(0xffffffffu, q, o);
    }
    __shared__ float ws[8], wq[8];
    if ((tid & 31) == 0){ ws[tid>>5] = s; wq[tid>>5] = q; }
    __syncthreads();
    s = ws[0]+ws[1]+ws[2]+ws[3]+ws[4]+ws[5]+ws[6]+ws[7];
    q = wq[0]+wq[1]+wq[2]+wq[3]+wq[4]+wq[5]+wq[6]+wq[7];
    float mu  = s*(1.f/1024.f);
    float var = q*(1.f/1024.f) - mu*mu;
    float rstd = rsqrtf(var + 1e-6f);
    float4 sm = *reinterpret_cast<const float4*>(&g_mod[b*6144 + 3*D_ + tid*4]);
    float4 sa = *reinterpret_cast<const float4*>(&b_ada[3*D_ + tid*4]);
    float4 cm = *reinterpret_cast<const float4*>(&g_mod[b*6144 + 4*D_ + tid*4]);
    float4 ca = *reinterpret_cast<const float4*>(&b_ada[4*D_ + tid*4]);
    float h0 = (v0-mu)*rstd*(1.f+cm.x+ca.x) + sm.x+sa.x;
    float h1 = (v1-mu)*rstd*(1.f+cm.y+ca.y) + sm.y+sa.y;
    float h2 = (v2-mu)*rstd*(1.f+cm.z+ca.z) + sm.z+sa.z;
    float h3 = (v3-mu)*rstd*(1.f+cm.w+ca.w) + sm.w+sa.w;
    __half2* ha = reinterpret_cast<__half2*>(&g_a[(size_t)r*D_ + tid*4]);
    ha[0] = __floats2half2_rn(h0,h1);
    ha[1] = __floats2half2_rn(h2,h3);
}

// ---------------- launch ------------------------------------------------------
extern "C" void kernel_launch(void* const* d_in, const int* in_sizes, int n_in,
                              void* d_out, int out_size) {
    const float* x        = (const float*)d_in[0];
    const float* c        = (const float*)d_in[1];
    const float* w_ada    = (const float*)d_in[2];
    const float* b_ada    = (const float*)d_in[3];
    const float* w_router = (const float*)d_in[4];
    const float* tm_w1    = (const float*)d_in[5];
    const float* tm_b1    = (const float*)d_in[6];
    const float* tm_w2    = (const float*)d_in[7];
    const float* tm_b2    = (const float*)d_in[8];
    const float* cm_w1    = (const float*)d_in[9];
    const float* cm_b1    = (const float*)d_in[10];
    const float* cm_w2    = (const float*)d_in[11];
    const float* cm_b2    = (const float*)d_in[12];
    const float* mlp_w1   = (const float*)d_in[13];
    const float* mlp_b1   = (const float*)d_in[14];
    const float* mlp_w2   = (const float*)d_in[15];
    const float* mlp_b2   = (const float*)d_in[16];
    float* outp = (float*)d_out;

    static cudaStream_t s2 = nullptr;
    static cudaEvent_t evF = nullptr, evJ = nullptr;
    static int attr_done = 0;
    if (!attr_done){
        cudaFuncSetAttribute(tgemm<T_TOK1>, cudaFuncAttributeMaxDynamicSharedMemorySize, SMEM_BYTES);
        cudaFuncSetAttribute(tgemm<T_TOK2>, cudaFuncAttributeMaxDynamicSharedMemorySize, SMEM_BYTES);
        cudaFuncSetAttribute(tgemm<T_CH1>,  cudaFuncAttributeMaxDynamicSharedMemorySize, SMEM_BYTES);
        cudaFuncSetAttribute(tgemm<T_CH2>,  cudaFuncAttributeMaxDynamicSharedMemorySize, SMEM_BYTES);
        cudaFuncSetAttribute(tgemm<T_MLP1>, cudaFuncAttributeMaxDynamicSharedMemorySize, SMEM_BYTES);
        cudaFuncSetAttribute(tgemm<T_MLP2>, cudaFuncAttributeMaxDynamicSharedMemorySize, SMEM_BYTES);
        cudaFuncSetAttribute(tgemm<T_MOD>,  cudaFuncAttributeMaxDynamicSharedMemorySize, SMEM_BYTES);
        cudaStreamCreateWithFlags(&s2, cudaStreamNonBlocking);
        cudaEventCreateWithFlags(&evF, cudaEventDisableTiming);
        cudaEventCreateWithFlags(&evJ, cudaEventDisableTiming);
        attr_done = 1;
    }

    __half* wp;
    cudaGetSymbolAddress((void**)&wp, g_w);
    void *rinp;
    cudaGetSymbolAddress(&rinp, g_rin);

    // ---- fork: big expert/MLP weight conversion on side stream ----
    cudaEventRecord(evF, 0);
    cudaStreamWaitEvent(s2, evF, 0);
    wconv_w<<<43008, 256, 0, s2>>>(tm_w1, tm_w2, cm_w1, cm_w2, mlp_w1, mlp_w2, wp);
    cudaEventRecord(evJ, s2);

    // ---- main stream: critical path (ada weights -> mod -> LN -> route) ----
    cudaMemsetAsync(rinp, 0, B_*D_*sizeof(float));
    wconv_a<<<6272, 256>>>(w_ada, c, wp);
    tgemm<T_MOD><<<dim3(48, 1, 1), 256, SMEM_BYTES>>>(nullptr, nullptr, nullptr);
    ew1_kernel<<<B_*N_, 256>>>(x, b_ada);
    tsplit_ht<<<dim3(32, 8, 64), dim3(32,8)>>>();
    route_kernel<<<B_, 256>>>(w_router);

    // ---- join: expert weights must be ready before expert GEMMs ----
    cudaStreamWaitEvent(0, evJ, 0);

    // routed experts (fp16 tensor cores, gated per (sample, expert))
    tgemm<T_TOK1><<<dim3( 8, 8, B_*4), 256, SMEM_BYTES>>>(tm_b1, nullptr, nullptr);
    tgemm<T_CH1> <<<dim3(32, 2, B_*4), 256, SMEM_BYTES>>>(cm_b1, nullptr, nullptr);
    tgemm<T_TOK2><<<dim3( 2, 8, B_*4), 256, SMEM_BYTES>>>(tm_b2, nullptr, nullptr);
    tgemm<T_CH2> <<<dim3( 8, 2, B_*4), 256, SMEM_BYTES>>>(cm_b2, nullptr, nullptr);

    // residual + second LN/modulate (x1 staged in d_out)
    ew2_kernel<<<B_*N_, 256>>>(x, b_ada, outp);

    // dense MLP (fp16 tensor cores), second residual fused into MLP2 epilogue
    tgemm<T_MLP1><<<dim3(32, 128, 1), 256, SMEM_BYTES>>>(mlp_b1, nullptr, nullptr);
    tgemm<T_MLP2><<<dim3( 8, 128, 1), 256, SMEM_BYTES>>>(mlp_b2, b_ada, outp);

    // aux scalar (independent; fills MLP tail)
    aux_kernel<<<1, 32>>>(outp, out_size);
}